// round 2
// baseline (speedup 1.0000x reference)
#include <cuda_runtime.h>
#include <cuda_bf16.h>
#include <math.h>

#define Tn 2048
#define Dn 1024
#define En 8
#define Fn 2048
#define Vn 32000
#define CAPn 640

// ---------------- device scratch (no allocations allowed) ----------------
__device__ float g_hA[Tn * Dn];
__device__ float g_hB[Tn * Dn];
__device__ int   g_top2[Tn * 2];
__device__ float g_topw[Tn * 2];
__device__ float g_wkept[Tn * 2];
__device__ int   g_elist[En * CAPn];
__device__ float g_ew[En * CAPn];
__device__ int   g_ecnt[En];
__device__ float g_hid[(size_t)En * CAPn * Fn];   // 42 MB activated hidden scratch

// ---------------- packed fp32x2 helpers (Blackwell sm_103a) ----------------
__device__ __forceinline__ unsigned long long pk2(float x) {
    unsigned long long r;
    asm("mov.b64 %0, {%1, %1};" : "=l"(r) : "f"(x));
    return r;
}
__device__ __forceinline__ void upk2(unsigned long long v, float& lo, float& hi) {
    asm("mov.b64 {%0, %1}, %2;" : "=f"(lo), "=f"(hi) : "l"(v));
}
__device__ __forceinline__ unsigned long long ffma2(unsigned long long a,
                                                    unsigned long long b,
                                                    unsigned long long c) {
    unsigned long long d;
    asm("fma.rn.f32x2 %0, %1, %2, %3;" : "=l"(d) : "l"(a), "l"(b), "l"(c));
    return d;
}
__device__ __forceinline__ float gelu_t(float x) {
    // jax.nn.gelu default (approximate=True, tanh form)
    float u = 0.7978845608028654f * (x + 0.044715f * x * x * x);
    return 0.5f * x * (1.0f + tanhf(u));
}

// ---------------- embedding gather ----------------
__global__ void k_embed(const int* __restrict__ ids, const float* __restrict__ ew) {
    int i = blockIdx.x * blockDim.x + threadIdx.x;        // over Tn*Dn/4
    int t = i / (Dn / 4);
    int d4 = i % (Dn / 4);
    float4 v = ((const float4*)(ew + (size_t)ids[t] * Dn))[d4];
    ((float4*)(g_hA + (size_t)t * Dn))[d4] = v;
}

// ---------------- router: logits, softmax, exact top-2 ----------------
__global__ void k_router(const float* __restrict__ h, const float* __restrict__ rw) {
    int t = blockIdx.x;
    int lane = threadIdx.x & 31;
    int w = threadIdx.x >> 5;                              // expert index (8 warps)
    const float* hr = h + (size_t)t * Dn;
    float acc = 0.f;
    for (int d = lane; d < Dn; d += 32) acc += hr[d] * rw[d * En + w];
    #pragma unroll
    for (int o = 16; o; o >>= 1) acc += __shfl_xor_sync(0xFFFFFFFFu, acc, o);
    __shared__ float lg[En];
    if (lane == 0) lg[w] = acc;
    __syncthreads();
    if (threadIdx.x == 0) {
        float l[En];
        #pragma unroll
        for (int e = 0; e < En; e++) l[e] = lg[e];
        float m = l[0];
        #pragma unroll
        for (int e = 1; e < En; e++) m = fmaxf(m, l[e]);
        float p[En], s = 0.f;
        #pragma unroll
        for (int e = 0; e < En; e++) { p[e] = expf(l[e] - m); s += p[e]; }
        float inv = 1.0f / s;
        // top-2 with lax.top_k tie semantics (strict >, first occurrence)
        int i0 = 0;
        #pragma unroll
        for (int e = 1; e < En; e++) if (l[e] > l[i0]) i0 = e;
        int i1 = -1;
        #pragma unroll
        for (int e = 0; e < En; e++) {
            if (e == i0) continue;
            if (i1 < 0 || l[e] > l[i1]) i1 = e;
        }
        g_top2[2 * t] = i0;
        g_top2[2 * t + 1] = i1;
        g_topw[2 * t] = p[i0] * inv;
        g_topw[2 * t + 1] = p[i1] * inv;
        g_wkept[2 * t] = 0.f;
        g_wkept[2 * t + 1] = 0.f;
    }
}

// ---------------- capacity scan: warp e scans expert e sequentially ----------------
__global__ void k_scan() {
    int lane = threadIdx.x & 31;
    int e = threadIdx.x >> 5;
    if (e >= En) return;
    int base = 0;
    for (int t0 = 0; t0 < Tn; t0 += 32) {
        int t = t0 + lane;
        int a = g_top2[2 * t], b = g_top2[2 * t + 1];
        int j = (a == e) ? 0 : ((b == e) ? 1 : -1);
        unsigned bal = __ballot_sync(0xFFFFFFFFu, j >= 0);
        int rank = base + __popc(bal & (0xFFFFFFFFu >> (31 - lane)));  // inclusive
        if (j >= 0 && rank <= CAPn) {
            int slot = rank - 1;
            g_elist[e * CAPn + slot] = t;
            float wv = g_topw[2 * t + j];
            g_ew[e * CAPn + slot] = wv;
            g_wkept[2 * t + j] = wv;
        }
        base += __popc(bal);
    }
    if (lane == 0) g_ecnt[e] = base < CAPn ? base : CAPn;
}

// ---------------- hout = hin * (1 - rho) ----------------
__global__ void k_scale(const float* __restrict__ hin, float* __restrict__ hout) {
    int t = blockIdx.x;
    float s = 1.0f - (g_wkept[2 * t] + g_wkept[2 * t + 1]);
    float4 v = ((const float4*)(hin + (size_t)t * Dn))[threadIdx.x];
    v.x *= s; v.y *= s; v.z *= s; v.w *= s;
    ((float4*)(hout + (size_t)t * Dn))[threadIdx.x] = v;
}

// ---------------- GEMM1: hid = gelu(X_e @ w1[e]),  X gathered by elist ----------------
// BM=64 BN=128 BK=16, 256 thr, micro 8x4 with m-paired FFMA2
__global__ __launch_bounds__(256) void k_gemm1(const float* __restrict__ h,
                                               const float* __restrict__ w1) {
    const int e = blockIdx.z;
    const int cnt = g_ecnt[e];
    const int m0 = blockIdx.y * 64;
    if (m0 >= cnt) return;
    const int n0 = blockIdx.x * 128;
    const float* W = w1 + (size_t)e * Dn * Fn;
    __shared__ float As[16][64];
    __shared__ float Bs[16][128];
    const int tid = threadIdx.x;
    const int ar = tid >> 2, ak = (tid & 3) << 2;
    const int row = m0 + ar;
    const float* Arow = (row < cnt) ? (h + (size_t)g_elist[e * CAPn + row] * Dn) : (const float*)0;
    const int bn = (tid & 31) << 2, bk = tid >> 5;
    const int mm = (tid >> 5) << 3, nn = (tid & 31) << 2;
    unsigned long long acc[4][4];
    #pragma unroll
    for (int i = 0; i < 4; i++)
        #pragma unroll
        for (int j = 0; j < 4; j++) acc[i][j] = 0ULL;

    for (int k0 = 0; k0 < Dn; k0 += 16) {
        float4 av = Arow ? *(const float4*)(Arow + k0 + ak) : make_float4(0.f, 0.f, 0.f, 0.f);
        As[ak][ar] = av.x; As[ak + 1][ar] = av.y; As[ak + 2][ar] = av.z; As[ak + 3][ar] = av.w;
        #pragma unroll
        for (int p = 0; p < 2; p++)
            *(float4*)&Bs[bk + p * 8][bn] =
                *(const float4*)(W + (size_t)(k0 + bk + p * 8) * Fn + n0 + bn);
        __syncthreads();
        #pragma unroll
        for (int kk = 0; kk < 16; kk++) {
            const unsigned long long* ap = (const unsigned long long*)&As[kk][mm];
            float4 bf = *(const float4*)&Bs[kk][nn];
            unsigned long long b0 = pk2(bf.x), b1 = pk2(bf.y), b2 = pk2(bf.z), b3 = pk2(bf.w);
            #pragma unroll
            for (int i = 0; i < 4; i++) {
                unsigned long long a = ap[i];
                acc[i][0] = ffma2(a, b0, acc[i][0]);
                acc[i][1] = ffma2(a, b1, acc[i][1]);
                acc[i][2] = ffma2(a, b2, acc[i][2]);
                acc[i][3] = ffma2(a, b3, acc[i][3]);
            }
        }
        __syncthreads();
    }
    float* Hd = g_hid + (size_t)e * CAPn * Fn;
    #pragma unroll
    for (int i = 0; i < 4; i++) {
        int r0 = m0 + mm + 2 * i, r1 = r0 + 1;
        #pragma unroll
        for (int j = 0; j < 4; j++) {
            float lo, hi;
            upk2(acc[i][j], lo, hi);
            if (r0 < cnt) Hd[(size_t)r0 * Fn + n0 + nn + j] = gelu_t(lo);
            if (r1 < cnt) Hd[(size_t)r1 * Fn + n0 + nn + j] = gelu_t(hi);
        }
    }
}

// ---------------- GEMM2: out = hid @ w2[e], rho-weighted atomic scatter ----------------
__global__ __launch_bounds__(256) void k_gemm2(const float* __restrict__ w2,
                                               float* __restrict__ hout) {
    const int e = blockIdx.z;
    const int cnt = g_ecnt[e];
    const int m0 = blockIdx.y * 64;
    if (m0 >= cnt) return;
    const int n0 = blockIdx.x * 128;
    const float* A = g_hid + (size_t)e * CAPn * Fn;
    const float* W = w2 + (size_t)e * Fn * Dn;
    __shared__ float As[16][64];
    __shared__ float Bs[16][128];
    const int tid = threadIdx.x;
    const int ar = tid >> 2, ak = (tid & 3) << 2;
    const float* Arow = A + (size_t)(m0 + ar) * Fn;   // always inside scratch buffer
    const int bn = (tid & 31) << 2, bk = tid >> 5;
    const int mm = (tid >> 5) << 3, nn = (tid & 31) << 2;
    unsigned long long acc[4][4];
    #pragma unroll
    for (int i = 0; i < 4; i++)
        #pragma unroll
        for (int j = 0; j < 4; j++) acc[i][j] = 0ULL;

    for (int k0 = 0; k0 < Fn; k0 += 16) {
        float4 av = *(const float4*)(Arow + k0 + ak);
        As[ak][ar] = av.x; As[ak + 1][ar] = av.y; As[ak + 2][ar] = av.z; As[ak + 3][ar] = av.w;
        #pragma unroll
        for (int p = 0; p < 2; p++)
            *(float4*)&Bs[bk + p * 8][bn] =
                *(const float4*)(W + (size_t)(k0 + bk + p * 8) * Dn + n0 + bn);
        __syncthreads();
        #pragma unroll
        for (int kk = 0; kk < 16; kk++) {
            const unsigned long long* ap = (const unsigned long long*)&As[kk][mm];
            float4 bf = *(const float4*)&Bs[kk][nn];
            unsigned long long b0 = pk2(bf.x), b1 = pk2(bf.y), b2 = pk2(bf.z), b3 = pk2(bf.w);
            #pragma unroll
            for (int i = 0; i < 4; i++) {
                unsigned long long a = ap[i];
                acc[i][0] = ffma2(a, b0, acc[i][0]);
                acc[i][1] = ffma2(a, b1, acc[i][1]);
                acc[i][2] = ffma2(a, b2, acc[i][2]);
                acc[i][3] = ffma2(a, b3, acc[i][3]);
            }
        }
        __syncthreads();
    }
    #pragma unroll
    for (int i = 0; i < 4; i++) {
        int r0 = m0 + mm + 2 * i, r1 = r0 + 1;
        int tok0 = 0, tok1 = 0;
        float w0 = 0.f, w1v = 0.f;
        if (r0 < cnt) { tok0 = g_elist[e * CAPn + r0]; w0 = g_ew[e * CAPn + r0]; }
        if (r1 < cnt) { tok1 = g_elist[e * CAPn + r1]; w1v = g_ew[e * CAPn + r1]; }
        #pragma unroll
        for (int j = 0; j < 4; j++) {
            float lo, hi;
            upk2(acc[i][j], lo, hi);
            if (r0 < cnt) atomicAdd(&hout[(size_t)tok0 * Dn + n0 + nn + j], w0 * lo);
            if (r1 < cnt) atomicAdd(&hout[(size_t)tok1 * Dn + n0 + nn + j], w1v * hi);
        }
    }
}

// ---------------- final rmsnorm ----------------
__global__ void k_rms(const float* __restrict__ hin, const float* __restrict__ lnw,
                      float* __restrict__ hout) {
    int t = blockIdx.x;
    int lane = threadIdx.x & 31, wid = threadIdx.x >> 5;
    float4 v = ((const float4*)(hin + (size_t)t * Dn))[threadIdx.x];
    float s = v.x * v.x + v.y * v.y + v.z * v.z + v.w * v.w;
    #pragma unroll
    for (int o = 16; o; o >>= 1) s += __shfl_xor_sync(0xFFFFFFFFu, s, o);
    __shared__ float red[8];
    if (lane == 0) red[wid] = s;
    __syncthreads();
    float tot = 0.f;
    #pragma unroll
    for (int i = 0; i < 8; i++) tot += red[i];
    float sc = rsqrtf(tot * (1.0f / Dn) + 1e-6f);
    float4 w = ((const float4*)lnw)[threadIdx.x];
    v.x *= sc * w.x; v.y *= sc * w.y; v.z *= sc * w.z; v.w *= sc * w.w;
    ((float4*)(hout + (size_t)t * Dn))[threadIdx.x] = v;
}

// ---------------- tied projection: C[t,v] = hn_t . embed_v (NT) ----------------
// BM=128 BN=128 BK=16, 256 thr, micro 8x8 with m-paired FFMA2
__global__ __launch_bounds__(256) void k_proj(const float* __restrict__ A,
                                              const float* __restrict__ B,
                                              float* __restrict__ C) {
    const int n0 = blockIdx.x * 128;   // vocab
    const int m0 = blockIdx.y * 128;   // tokens
    __shared__ float As[16][128];
    __shared__ float Bs[16][128];
    const int tid = threadIdx.x;
    const int lr = tid >> 2, lk = (tid & 3) << 2;
    const int mm = (tid >> 4) << 3, nn = (tid & 15) << 3;
    unsigned long long acc[4][8];
    #pragma unroll
    for (int i = 0; i < 4; i++)
        #pragma unroll
        for (int j = 0; j < 8; j++) acc[i][j] = 0ULL;

    for (int k0 = 0; k0 < Dn; k0 += 16) {
        #pragma unroll
        for (int p = 0; p < 2; p++) {
            int r = lr + p * 64;
            float4 av = *(const float4*)(A + (size_t)(m0 + r) * Dn + k0 + lk);
            As[lk][r] = av.x; As[lk + 1][r] = av.y; As[lk + 2][r] = av.z; As[lk + 3][r] = av.w;
            float4 bv = *(const float4*)(B + (size_t)(n0 + r) * Dn + k0 + lk);
            Bs[lk][r] = bv.x; Bs[lk + 1][r] = bv.y; Bs[lk + 2][r] = bv.z; Bs[lk + 3][r] = bv.w;
        }
        __syncthreads();
        #pragma unroll
        for (int kk = 0; kk < 16; kk++) {
            const unsigned long long* ap = (const unsigned long long*)&As[kk][mm];
            float4 b0 = *(const float4*)&Bs[kk][nn];
            float4 b1 = *(const float4*)&Bs[kk][nn + 4];
            unsigned long long bp[8] = {pk2(b0.x), pk2(b0.y), pk2(b0.z), pk2(b0.w),
                                        pk2(b1.x), pk2(b1.y), pk2(b1.z), pk2(b1.w)};
            #pragma unroll
            for (int i = 0; i < 4; i++) {
                unsigned long long a = ap[i];
                #pragma unroll
                for (int j = 0; j < 8; j++) acc[i][j] = ffma2(a, bp[j], acc[i][j]);
            }
        }
        __syncthreads();
    }
    #pragma unroll
    for (int i = 0; i < 4; i++) {
        float lo[8], hi[8];
        #pragma unroll
        for (int j = 0; j < 8; j++) upk2(acc[i][j], lo[j], hi[j]);
        size_t r0 = (size_t)(m0 + mm + 2 * i) * Vn + n0 + nn;
        size_t r1 = r0 + Vn;
        *(float4*)&C[r0]     = make_float4(lo[0], lo[1], lo[2], lo[3]);
        *(float4*)&C[r0 + 4] = make_float4(lo[4], lo[5], lo[6], lo[7]);
        *(float4*)&C[r1]     = make_float4(hi[0], hi[1], hi[2], hi[3]);
        *(float4*)&C[r1 + 4] = make_float4(hi[4], hi[5], hi[6], hi[7]);
    }
}

// ---------------- launch ----------------
extern "C" void kernel_launch(void* const* d_in, const int* in_sizes, int n_in,
                              void* d_out, int out_size) {
    (void)in_sizes; (void)n_in; (void)out_size;
    const int*   ids    = (const int*)d_in[0];
    const float* embed  = (const float*)d_in[1];
    const float* router = (const float*)d_in[2];
    const float* w1     = (const float*)d_in[3];
    const float* w2     = (const float*)d_in[4];
    const float* lnw    = (const float*)d_in[5];
    float* out = (float*)d_out;

    float *hA, *hB;
    cudaGetSymbolAddress((void**)&hA, g_hA);
    cudaGetSymbolAddress((void**)&hB, g_hB);

    k_embed<<<(Tn * Dn / 4) / 256, 256>>>(ids, embed);

    float* hin = hA;
    float* hout = hB;
    for (int hop = 0; hop < 2; hop++) {
        k_router<<<Tn, 256>>>(hin, router + (size_t)hop * Dn * En);
        k_scan<<<1, 256>>>();
        k_scale<<<Tn, 256>>>(hin, hout);
        k_gemm1<<<dim3(Fn / 128, CAPn / 64, En), 256>>>(hin, w1);
        k_gemm2<<<dim3(Dn / 128, CAPn / 64, En), 256>>>(w2, hout);
        float* tmp = hin; hin = hout; hout = tmp;
    }
    k_rms<<<Tn, 256>>>(hin, lnw, hout);
    k_proj<<<dim3(Vn / 128, Tn / 128), 256>>>(hout, embed, out);
}

// round 4
// speedup vs baseline: 1.5703x; 1.5703x over previous
#include <cuda_runtime.h>
#include <cuda_bf16.h>
#include <math.h>
#include <stdint.h>

#define Tn 2048
#define Dn 1024
#define En 8
#define Fn 2048
#define Vn 32000
#define CAPn 640

// ---------------- device scratch (no allocations allowed) ----------------
__device__ float g_hA[Tn * Dn];
__device__ float g_hB[Tn * Dn];
__device__ int   g_top2[Tn * 2];
__device__ float g_topw[Tn * 2];
__device__ float g_wkept[Tn * 2];
__device__ int   g_elist[En * CAPn];
__device__ float g_ew[En * CAPn];
__device__ int   g_ecnt[En];
__device__ float g_hid[(size_t)En * CAPn * Fn];          // 42 MB hidden scratch
__device__ __nv_bfloat16 g_Bh[(size_t)Vn * Dn];          // embed split hi
__device__ __nv_bfloat16 g_Bl[(size_t)Vn * Dn];          // embed split lo
__device__ __nv_bfloat16 g_Ah[Tn * Dn];                  // h_norm split hi
__device__ __nv_bfloat16 g_Al[Tn * Dn];                  // h_norm split lo

// ---------------- packed fp32x2 helpers ----------------
__device__ __forceinline__ unsigned long long pk2(float x) {
    unsigned long long r;
    asm("mov.b64 %0, {%1, %1};" : "=l"(r) : "f"(x));
    return r;
}
__device__ __forceinline__ void upk2(unsigned long long v, float& lo, float& hi) {
    asm("mov.b64 {%0, %1}, %2;" : "=f"(lo), "=f"(hi) : "l"(v));
}
__device__ __forceinline__ unsigned long long ffma2(unsigned long long a,
                                                    unsigned long long b,
                                                    unsigned long long c) {
    unsigned long long d;
    asm("fma.rn.f32x2 %0, %1, %2, %3;" : "=l"(d) : "l"(a), "l"(b), "l"(c));
    return d;
}
__device__ __forceinline__ float gelu_t(float x) {
    float u = 0.7978845608028654f * (x + 0.044715f * x * x * x);
    return 0.5f * x * (1.0f + tanhf(u));
}

// ---------------- hmma helpers (sm_80+ ISA, valid on plain sm_103) ----------------
__device__ __forceinline__ uint32_t s2u(const void* p) {
    uint32_t a;
    asm("{ .reg .u64 t; cvta.to.shared.u64 t, %1; cvt.u32.u64 %0, t; }" : "=r"(a) : "l"(p));
    return a;
}
__device__ __forceinline__ void ldsm4(uint32_t* r, uint32_t a) {
    asm volatile("ldmatrix.sync.aligned.m8n8.x4.shared.b16 {%0,%1,%2,%3}, [%4];"
                 : "=r"(r[0]), "=r"(r[1]), "=r"(r[2]), "=r"(r[3]) : "r"(a));
}
__device__ __forceinline__ void mma16816(float* c, const uint32_t* a, uint32_t b0, uint32_t b1) {
    asm volatile("mma.sync.aligned.m16n8k16.row.col.f32.bf16.bf16.f32 "
                 "{%0,%1,%2,%3}, {%4,%5,%6,%7}, {%8,%9}, {%0,%1,%2,%3};"
                 : "+f"(c[0]), "+f"(c[1]), "+f"(c[2]), "+f"(c[3])
                 : "r"(a[0]), "r"(a[1]), "r"(a[2]), "r"(a[3]), "r"(b0), "r"(b1));
}
__device__ __forceinline__ void cpa16(uint32_t dst, const void* src) {
    asm volatile("cp.async.cg.shared.global [%0], [%1], 16;" :: "r"(dst), "l"(src) : "memory");
}

// ---------------- embedding gather ----------------
__global__ void k_embed(const int* __restrict__ ids, const float* __restrict__ ew) {
    int i = blockIdx.x * blockDim.x + threadIdx.x;
    int t = i / (Dn / 4);
    int d4 = i % (Dn / 4);
    float4 v = ((const float4*)(ew + (size_t)ids[t] * Dn))[d4];
    ((float4*)(g_hA + (size_t)t * Dn))[d4] = v;
}

// ---------------- fp32 -> (bf16 hi, bf16 lo) split ----------------
__global__ void k_split(const float* __restrict__ src, __nv_bfloat16* __restrict__ hi,
                        __nv_bfloat16* __restrict__ lo, int n4) {
    int i = blockIdx.x * blockDim.x + threadIdx.x;
    if (i >= n4) return;
    float4 v = ((const float4*)src)[i];
    float x[4] = {v.x, v.y, v.z, v.w};
    unsigned short h[4], l[4];
    #pragma unroll
    for (int j = 0; j < 4; j++) {
        __nv_bfloat16 hb = __float2bfloat16_rn(x[j]);
        __nv_bfloat16 lb = __float2bfloat16_rn(x[j] - __bfloat162float(hb));
        h[j] = *(unsigned short*)&hb;
        l[j] = *(unsigned short*)&lb;
    }
    uint2 hp = make_uint2((uint32_t)h[0] | ((uint32_t)h[1] << 16),
                          (uint32_t)h[2] | ((uint32_t)h[3] << 16));
    uint2 lp = make_uint2((uint32_t)l[0] | ((uint32_t)l[1] << 16),
                          (uint32_t)l[2] | ((uint32_t)l[3] << 16));
    ((uint2*)hi)[i] = hp;
    ((uint2*)lo)[i] = lp;
}

// ---------------- router ----------------
__global__ void k_router(const float* __restrict__ h, const float* __restrict__ rw) {
    int t = blockIdx.x;
    int lane = threadIdx.x & 31;
    int w = threadIdx.x >> 5;
    const float* hr = h + (size_t)t * Dn;
    float acc = 0.f;
    for (int d = lane; d < Dn; d += 32) acc += hr[d] * rw[d * En + w];
    #pragma unroll
    for (int o = 16; o; o >>= 1) acc += __shfl_xor_sync(0xFFFFFFFFu, acc, o);
    __shared__ float lg[En];
    if (lane == 0) lg[w] = acc;
    __syncthreads();
    if (threadIdx.x == 0) {
        float l[En];
        #pragma unroll
        for (int e = 0; e < En; e++) l[e] = lg[e];
        float m = l[0];
        #pragma unroll
        for (int e = 1; e < En; e++) m = fmaxf(m, l[e]);
        float p[En], s = 0.f;
        #pragma unroll
        for (int e = 0; e < En; e++) { p[e] = expf(l[e] - m); s += p[e]; }
        float inv = 1.0f / s;
        int i0 = 0;
        #pragma unroll
        for (int e = 1; e < En; e++) if (l[e] > l[i0]) i0 = e;
        int i1 = -1;
        #pragma unroll
        for (int e = 0; e < En; e++) {
            if (e == i0) continue;
            if (i1 < 0 || l[e] > l[i1]) i1 = e;
        }
        g_top2[2 * t] = i0;
        g_top2[2 * t + 1] = i1;
        g_topw[2 * t] = p[i0] * inv;
        g_topw[2 * t + 1] = p[i1] * inv;
        g_wkept[2 * t] = 0.f;
        g_wkept[2 * t + 1] = 0.f;
    }
}

// ---------------- capacity scan ----------------
__global__ void k_scan() {
    int lane = threadIdx.x & 31;
    int e = threadIdx.x >> 5;
    if (e >= En) return;
    int base = 0;
    for (int t0 = 0; t0 < Tn; t0 += 32) {
        int t = t0 + lane;
        int a = g_top2[2 * t], b = g_top2[2 * t + 1];
        int j = (a == e) ? 0 : ((b == e) ? 1 : -1);
        unsigned bal = __ballot_sync(0xFFFFFFFFu, j >= 0);
        int rank = base + __popc(bal & (0xFFFFFFFFu >> (31 - lane)));
        if (j >= 0 && rank <= CAPn) {
            int slot = rank - 1;
            g_elist[e * CAPn + slot] = t;
            float wv = g_topw[2 * t + j];
            g_ew[e * CAPn + slot] = wv;
            g_wkept[2 * t + j] = wv;
        }
        base += __popc(bal);
    }
    if (lane == 0) g_ecnt[e] = base < CAPn ? base : CAPn;
}

// ---------------- hout = hin * (1 - rho) ----------------
__global__ void k_scale(const float* __restrict__ hin, float* __restrict__ hout) {
    int t = blockIdx.x;
    float s = 1.0f - (g_wkept[2 * t] + g_wkept[2 * t + 1]);
    float4 v = ((const float4*)(hin + (size_t)t * Dn))[threadIdx.x];
    v.x *= s; v.y *= s; v.z *= s; v.w *= s;
    ((float4*)(hout + (size_t)t * Dn))[threadIdx.x] = v;
}

// ---------------- GEMM1: hid = gelu(X_e @ w1[e]) ----------------
__global__ __launch_bounds__(256) void k_gemm1(const float* __restrict__ h,
                                               const float* __restrict__ w1) {
    const int e = blockIdx.z;
    const int cnt = g_ecnt[e];
    const int m0 = blockIdx.y * 64;
    if (m0 >= cnt) return;
    const int n0 = blockIdx.x * 128;
    const float* W = w1 + (size_t)e * Dn * Fn;
    __shared__ float As[16][64];
    __shared__ float Bs[16][128];
    const int tid = threadIdx.x;
    const int ar = tid >> 2, ak = (tid & 3) << 2;
    const int row = m0 + ar;
    const float* Arow = (row < cnt) ? (h + (size_t)g_elist[e * CAPn + row] * Dn) : (const float*)0;
    const int bn = (tid & 31) << 2, bk = tid >> 5;
    const int mm = (tid >> 5) << 3, nn = (tid & 31) << 2;
    unsigned long long acc[4][4];
    #pragma unroll
    for (int i = 0; i < 4; i++)
        #pragma unroll
        for (int j = 0; j < 4; j++) acc[i][j] = 0ULL;

    for (int k0 = 0; k0 < Dn; k0 += 16) {
        float4 av = Arow ? *(const float4*)(Arow + k0 + ak) : make_float4(0.f, 0.f, 0.f, 0.f);
        As[ak][ar] = av.x; As[ak + 1][ar] = av.y; As[ak + 2][ar] = av.z; As[ak + 3][ar] = av.w;
        #pragma unroll
        for (int p = 0; p < 2; p++)
            *(float4*)&Bs[bk + p * 8][bn] =
                *(const float4*)(W + (size_t)(k0 + bk + p * 8) * Fn + n0 + bn);
        __syncthreads();
        #pragma unroll
        for (int kk = 0; kk < 16; kk++) {
            const unsigned long long* ap = (const unsigned long long*)&As[kk][mm];
            float4 bf = *(const float4*)&Bs[kk][nn];
            unsigned long long b0 = pk2(bf.x), b1 = pk2(bf.y), b2 = pk2(bf.z), b3 = pk2(bf.w);
            #pragma unroll
            for (int i = 0; i < 4; i++) {
                unsigned long long a = ap[i];
                acc[i][0] = ffma2(a, b0, acc[i][0]);
                acc[i][1] = ffma2(a, b1, acc[i][1]);
                acc[i][2] = ffma2(a, b2, acc[i][2]);
                acc[i][3] = ffma2(a, b3, acc[i][3]);
            }
        }
        __syncthreads();
    }
    float* Hd = g_hid + (size_t)e * CAPn * Fn;
    #pragma unroll
    for (int i = 0; i < 4; i++) {
        int r0 = m0 + mm + 2 * i, r1 = r0 + 1;
        #pragma unroll
        for (int j = 0; j < 4; j++) {
            float lo, hi;
            upk2(acc[i][j], lo, hi);
            if (r0 < cnt) Hd[(size_t)r0 * Fn + n0 + nn + j] = gelu_t(lo);
            if (r1 < cnt) Hd[(size_t)r1 * Fn + n0 + nn + j] = gelu_t(hi);
        }
    }
}

// ---------------- GEMM2: out += rho * (hid @ w2[e]) ----------------
__global__ __launch_bounds__(256) void k_gemm2(const float* __restrict__ w2,
                                               float* __restrict__ hout) {
    const int e = blockIdx.z;
    const int cnt = g_ecnt[e];
    const int m0 = blockIdx.y * 64;
    if (m0 >= cnt) return;
    const int n0 = blockIdx.x * 128;
    const float* A = g_hid + (size_t)e * CAPn * Fn;
    const float* W = w2 + (size_t)e * Fn * Dn;
    __shared__ float As[16][64];
    __shared__ float Bs[16][128];
    const int tid = threadIdx.x;
    const int ar = tid >> 2, ak = (tid & 3) << 2;
    const float* Arow = A + (size_t)(m0 + ar) * Fn;
    const int bn = (tid & 31) << 2, bk = tid >> 5;
    const int mm = (tid >> 5) << 3, nn = (tid & 31) << 2;
    unsigned long long acc[4][4];
    #pragma unroll
    for (int i = 0; i < 4; i++)
        #pragma unroll
        for (int j = 0; j < 4; j++) acc[i][j] = 0ULL;

    for (int k0 = 0; k0 < Fn; k0 += 16) {
        float4 av = *(const float4*)(Arow + k0 + ak);
        As[ak][ar] = av.x; As[ak + 1][ar] = av.y; As[ak + 2][ar] = av.z; As[ak + 3][ar] = av.w;
        #pragma unroll
        for (int p = 0; p < 2; p++)
            *(float4*)&Bs[bk + p * 8][bn] =
                *(const float4*)(W + (size_t)(k0 + bk + p * 8) * Dn + n0 + bn);
        __syncthreads();
        #pragma unroll
        for (int kk = 0; kk < 16; kk++) {
            const unsigned long long* ap = (const unsigned long long*)&As[kk][mm];
            float4 bf = *(const float4*)&Bs[kk][nn];
            unsigned long long b0 = pk2(bf.x), b1 = pk2(bf.y), b2 = pk2(bf.z), b3 = pk2(bf.w);
            #pragma unroll
            for (int i = 0; i < 4; i++) {
                unsigned long long a = ap[i];
                acc[i][0] = ffma2(a, b0, acc[i][0]);
                acc[i][1] = ffma2(a, b1, acc[i][1]);
                acc[i][2] = ffma2(a, b2, acc[i][2]);
                acc[i][3] = ffma2(a, b3, acc[i][3]);
            }
        }
        __syncthreads();
    }
    #pragma unroll
    for (int i = 0; i < 4; i++) {
        int r0 = m0 + mm + 2 * i, r1 = r0 + 1;
        int tok0 = 0, tok1 = 0;
        float w0 = 0.f, w1v = 0.f;
        if (r0 < cnt) { tok0 = g_elist[e * CAPn + r0]; w0 = g_ew[e * CAPn + r0]; }
        if (r1 < cnt) { tok1 = g_elist[e * CAPn + r1]; w1v = g_ew[e * CAPn + r1]; }
        #pragma unroll
        for (int j = 0; j < 4; j++) {
            float lo, hi;
            upk2(acc[i][j], lo, hi);
            if (r0 < cnt) atomicAdd(&hout[(size_t)tok0 * Dn + n0 + nn + j], w0 * lo);
            if (r1 < cnt) atomicAdd(&hout[(size_t)tok1 * Dn + n0 + nn + j], w1v * hi);
        }
    }
}

// ---------------- final rmsnorm ----------------
__global__ void k_rms(const float* __restrict__ hin, const float* __restrict__ lnw,
                      float* __restrict__ hout) {
    int t = blockIdx.x;
    int lane = threadIdx.x & 31, wid = threadIdx.x >> 5;
    float4 v = ((const float4*)(hin + (size_t)t * Dn))[threadIdx.x];
    float s = v.x * v.x + v.y * v.y + v.z * v.z + v.w * v.w;
    #pragma unroll
    for (int o = 16; o; o >>= 1) s += __shfl_xor_sync(0xFFFFFFFFu, s, o);
    __shared__ float red[8];
    if (lane == 0) red[wid] = s;
    __syncthreads();
    float tot = 0.f;
    #pragma unroll
    for (int i = 0; i < 8; i++) tot += red[i];
    float sc = rsqrtf(tot * (1.0f / Dn) + 1e-6f);
    float4 w = ((const float4*)lnw)[threadIdx.x];
    v.x *= sc * w.x; v.y *= sc * w.y; v.z *= sc * w.z; v.w *= sc * w.w;
    ((float4*)(hout + (size_t)t * Dn))[threadIdx.x] = v;
}

// ---------------- tied projection via mma.sync bf16, 3-term split ----------------
// C = Ah.Bh + Al.Bh + Ah.Bl, fp32 accumulators. BM=BN=128, BK=32, 8 warps (4m x 2n).
#define ROWB 80                      // padded smem row: 32 bf16 data + 8 pad (80B)
#define ARRB (128 * ROWB)            // 10240 B per operand tile
#define STAGEB (4 * ARRB)            // Ah,Al,Bh,Bl per stage = 40960 B
#define NCHK (Dn / 32)               // 32 k-chunks

__global__ __launch_bounds__(256, 1)
void k_proj_hmma(const __nv_bfloat16* __restrict__ Ah, const __nv_bfloat16* __restrict__ Al,
                 const __nv_bfloat16* __restrict__ Bh, const __nv_bfloat16* __restrict__ Bl,
                 float* __restrict__ C) {
    extern __shared__ char smraw[];
    const uint32_t sbase = s2u(smraw);
    const int tid = threadIdx.x;
    const int lane = tid & 31;
    const int wm = (tid >> 5) & 3;           // warp m (4)
    const int wn = tid >> 7;                 // warp n (2)
    const int m0 = blockIdx.x * 128;         // token tile (inner for L2 B-reuse)
    const int n0 = blockIdx.y * 128;         // vocab tile

    float acc[2][8][4];
    #pragma unroll
    for (int i = 0; i < 2; i++)
        #pragma unroll
        for (int j = 0; j < 8; j++)
            #pragma unroll
            for (int q = 0; q < 4; q++) acc[i][j][q] = 0.f;

    // ---- stage loader: 4 operand tiles of 128 rows x 64B via cp.async ----
    auto load_stage = [&](int c, int st) {
        const int kb = c * 32;
        const uint32_t sb = sbase + st * STAGEB;
        #pragma unroll
        for (int half = 0; half < 2; half++) {
            int id = tid + half * 256;          // 512 x 16B segs per operand
            int row = id >> 2, seg = id & 3;
            uint32_t off = (uint32_t)(row * ROWB + seg * 16);
            size_t ga = (size_t)(m0 + row) * Dn + kb + seg * 8;
            size_t gb = (size_t)(n0 + row) * Dn + kb + seg * 8;
            cpa16(sb + off, Ah + ga);
            cpa16(sb + ARRB + off, Al + ga);
            cpa16(sb + 2 * ARRB + off, Bh + gb);
            cpa16(sb + 3 * ARRB + off, Bl + gb);
        }
        asm volatile("cp.async.commit_group;" ::: "memory");
    };

    load_stage(0, 0);
    load_stage(1, 1);

    // lane->address components (constant over loop)
    const int a_lr = lane & 15;                      // A row within m16
    const int a_lc = ((lane >> 4) << 3);             // A col 0/8
    const int b_nr = ((lane >> 4) << 3) + (lane & 7);// B n-row within 16
    const int b_kc = (lane & 8);                     // B col 0/8

    for (int c = 0; c < NCHK; c++) {
        const int st = c & 1;
        if (c + 1 < NCHK) asm volatile("cp.async.wait_group 1;" ::: "memory");
        else              asm volatile("cp.async.wait_group 0;" ::: "memory");
        __syncthreads();
        const uint32_t sb = sbase + st * STAGEB;

        #pragma unroll
        for (int k16 = 0; k16 < 32; k16 += 16) {
            uint32_t ah[2][4], al[2][4];
            #pragma unroll
            for (int mi = 0; mi < 2; mi++) {
                uint32_t aoff = (uint32_t)((wm * 32 + mi * 16 + a_lr) * ROWB + (k16 + a_lc) * 2);
                ldsm4(ah[mi], sb + aoff);
                ldsm4(al[mi], sb + ARRB + aoff);
            }
            #pragma unroll
            for (int ng = 0; ng < 4; ng++) {
                uint32_t boff = (uint32_t)((wn * 64 + ng * 16 + b_nr) * ROWB + (k16 + b_kc) * 2);
                uint32_t bh[4], bl[4];
                ldsm4(bh, sb + 2 * ARRB + boff);
                ldsm4(bl, sb + 3 * ARRB + boff);
                #pragma unroll
                for (int hv = 0; hv < 2; hv++) {
                    const int nj = ng * 2 + hv;
                    #pragma unroll
                    for (int mi = 0; mi < 2; mi++) {
                        mma16816(acc[mi][nj], ah[mi], bh[2 * hv], bh[2 * hv + 1]);
                        mma16816(acc[mi][nj], al[mi], bh[2 * hv], bh[2 * hv + 1]);
                        mma16816(acc[mi][nj], ah[mi], bl[2 * hv], bl[2 * hv + 1]);
                    }
                }
            }
        }
        __syncthreads();
        if (c + 2 < NCHK) load_stage(c + 2, st);
    }

    // ---- epilogue ----
    const int g = lane >> 2, t2 = (lane & 3) << 1;
    #pragma unroll
    for (int mi = 0; mi < 2; mi++) {
        #pragma unroll
        for (int nj = 0; nj < 8; nj++) {
            int r = m0 + wm * 32 + mi * 16 + g;
            int col = n0 + wn * 64 + nj * 8 + t2;
            *(float2*)&C[(size_t)r * Vn + col] = make_float2(acc[mi][nj][0], acc[mi][nj][1]);
            *(float2*)&C[(size_t)(r + 8) * Vn + col] = make_float2(acc[mi][nj][2], acc[mi][nj][3]);
        }
    }
}

// ---------------- launch ----------------
extern "C" void kernel_launch(void* const* d_in, const int* in_sizes, int n_in,
                              void* d_out, int out_size) {
    (void)in_sizes; (void)n_in; (void)out_size;
    const int*   ids    = (const int*)d_in[0];
    const float* embed  = (const float*)d_in[1];
    const float* router = (const float*)d_in[2];
    const float* w1     = (const float*)d_in[3];
    const float* w2     = (const float*)d_in[4];
    const float* lnw    = (const float*)d_in[5];
    float* out = (float*)d_out;

    float *hA, *hB;
    __nv_bfloat16 *pBh, *pBl, *pAh, *pAl;
    cudaGetSymbolAddress((void**)&hA, g_hA);
    cudaGetSymbolAddress((void**)&hB, g_hB);
    cudaGetSymbolAddress((void**)&pBh, g_Bh);
    cudaGetSymbolAddress((void**)&pBl, g_Bl);
    cudaGetSymbolAddress((void**)&pAh, g_Ah);
    cudaGetSymbolAddress((void**)&pAl, g_Al);

    // embed bf16 split (independent of MoE path)
    k_split<<<(Vn * Dn / 4 + 255) / 256, 256>>>(embed, pBh, pBl, Vn * Dn / 4);

    k_embed<<<(Tn * Dn / 4) / 256, 256>>>(ids, embed);

    float* hin = hA;
    float* hout = hB;
    for (int hop = 0; hop < 2; hop++) {
        k_router<<<Tn, 256>>>(hin, router + (size_t)hop * Dn * En);
        k_scan<<<1, 256>>>();
        k_scale<<<Tn, 256>>>(hin, hout);
        k_gemm1<<<dim3(Fn / 128, CAPn / 64, En), 256>>>(hin, w1);
        k_gemm2<<<dim3(Dn / 128, CAPn / 64, En), 256>>>(w2, hout);
        float* tmp = hin; hin = hout; hout = tmp;
    }
    k_rms<<<Tn, 256>>>(hin, lnw, hout);
    k_split<<<(Tn * Dn / 4 + 255) / 256, 256>>>(hout, pAh, pAl, Tn * Dn / 4);

    cudaFuncSetAttribute(k_proj_hmma, cudaFuncAttributeMaxDynamicSharedMemorySize, 2 * STAGEB);
    k_proj_hmma<<<dim3(Tn / 128, Vn / 128), 256, 2 * STAGEB>>>(pAh, pAl, pBh, pBl, out);
}

// round 5
// speedup vs baseline: 2.2173x; 1.4120x over previous
#include <cuda_runtime.h>
#include <cuda_bf16.h>
#include <math.h>
#include <stdint.h>

#define Tn 2048
#define Dn 1024
#define En 8
#define Fn 2048
#define Vn 32000
#define CAPn 640

// ---------------- device scratch (no allocations allowed) ----------------
__device__ float g_hA[Tn * Dn];
__device__ float g_hB[Tn * Dn];
__device__ int   g_top2[Tn * 2];
__device__ float g_topw[Tn * 2];
__device__ float g_wkept[Tn * 2];
__device__ int   g_elist[En * CAPn];
__device__ float g_ew[En * CAPn];
__device__ int   g_ecnt[En];
__device__ __nv_bfloat16 g_Bh[(size_t)Vn * Dn];          // embed split hi
__device__ __nv_bfloat16 g_Bl[(size_t)Vn * Dn];          // embed split lo
__device__ __nv_bfloat16 g_Ah[Tn * Dn];                  // h split hi (per hop + final)
__device__ __nv_bfloat16 g_Al[Tn * Dn];                  // h split lo
__device__ __nv_bfloat16 g_w1h[(size_t)En * Fn * Dn];    // w1^T split hi  [E][F][D]
__device__ __nv_bfloat16 g_w1l[(size_t)En * Fn * Dn];
__device__ __nv_bfloat16 g_w2h[(size_t)En * Dn * Fn];    // w2^T split hi  [E][D][F]
__device__ __nv_bfloat16 g_w2l[(size_t)En * Dn * Fn];
__device__ __nv_bfloat16 g_hidh[(size_t)En * CAPn * Fn]; // gelu(hid) split hi
__device__ __nv_bfloat16 g_hidl[(size_t)En * CAPn * Fn];

__device__ __forceinline__ float gelu_t(float x) {
    float u = 0.7978845608028654f * (x + 0.044715f * x * x * x);
    return 0.5f * x * (1.0f + tanhf(u));
}

// ---------------- hmma helpers (sm_80+ ISA, valid on plain sm_103) ----------------
__device__ __forceinline__ uint32_t s2u(const void* p) {
    uint32_t a;
    asm("{ .reg .u64 t; cvta.to.shared.u64 t, %1; cvt.u32.u64 %0, t; }" : "=r"(a) : "l"(p));
    return a;
}
__device__ __forceinline__ void ldsm4(uint32_t* r, uint32_t a) {
    asm volatile("ldmatrix.sync.aligned.m8n8.x4.shared.b16 {%0,%1,%2,%3}, [%4];"
                 : "=r"(r[0]), "=r"(r[1]), "=r"(r[2]), "=r"(r[3]) : "r"(a));
}
__device__ __forceinline__ void mma16816(float* c, const uint32_t* a, uint32_t b0, uint32_t b1) {
    asm volatile("mma.sync.aligned.m16n8k16.row.col.f32.bf16.bf16.f32 "
                 "{%0,%1,%2,%3}, {%4,%5,%6,%7}, {%8,%9}, {%0,%1,%2,%3};"
                 : "+f"(c[0]), "+f"(c[1]), "+f"(c[2]), "+f"(c[3])
                 : "r"(a[0]), "r"(a[1]), "r"(a[2]), "r"(a[3]), "r"(b0), "r"(b1));
}
__device__ __forceinline__ void cpa16(uint32_t dst, const void* src) {
    asm volatile("cp.async.cg.shared.global [%0], [%1], 16;" :: "r"(dst), "l"(src) : "memory");
}
__device__ __forceinline__ void bsplit(float x, unsigned short& h, unsigned short& l) {
    __nv_bfloat16 hb = __float2bfloat16_rn(x);
    __nv_bfloat16 lb = __float2bfloat16_rn(x - __bfloat162float(hb));
    h = *(unsigned short*)&hb;
    l = *(unsigned short*)&lb;
}

// ---------------- embedding gather ----------------
__global__ void k_embed(const int* __restrict__ ids, const float* __restrict__ ew) {
    int i = blockIdx.x * blockDim.x + threadIdx.x;
    int t = i / (Dn / 4);
    int d4 = i % (Dn / 4);
    float4 v = ((const float4*)(ew + (size_t)ids[t] * Dn))[d4];
    ((float4*)(g_hA + (size_t)t * Dn))[d4] = v;
}

// ---------------- fp32 -> (bf16 hi, bf16 lo) split, same layout ----------------
__global__ void k_split(const float* __restrict__ src, __nv_bfloat16* __restrict__ hi,
                        __nv_bfloat16* __restrict__ lo, int n4) {
    int i = blockIdx.x * blockDim.x + threadIdx.x;
    if (i >= n4) return;
    float4 v = ((const float4*)src)[i];
    float x[4] = {v.x, v.y, v.z, v.w};
    unsigned short h[4], l[4];
    #pragma unroll
    for (int j = 0; j < 4; j++) bsplit(x[j], h[j], l[j]);
    ((uint2*)hi)[i] = make_uint2((uint32_t)h[0] | ((uint32_t)h[1] << 16),
                                 (uint32_t)h[2] | ((uint32_t)h[3] << 16));
    ((uint2*)lo)[i] = make_uint2((uint32_t)l[0] | ((uint32_t)l[1] << 16),
                                 (uint32_t)l[2] | ((uint32_t)l[3] << 16));
}

// ---------------- transpose + split: src [E][R][C] fp32 -> hi/lo [E][C][R] bf16 ----------------
__global__ void k_tsplit(const float* __restrict__ src, __nv_bfloat16* __restrict__ hi,
                         __nv_bfloat16* __restrict__ lo, int R, int C) {
    __shared__ float t[32][33];
    int e = blockIdx.z;
    const float* S = src + (size_t)e * R * C;
    __nv_bfloat16* H = hi + (size_t)e * R * C;
    __nv_bfloat16* L = lo + (size_t)e * R * C;
    int c0 = blockIdx.x * 32, r0 = blockIdx.y * 32;
    int tx = threadIdx.x, ty = threadIdx.y;
    #pragma unroll
    for (int j = 0; j < 32; j += 8)
        t[ty + j][tx] = S[(size_t)(r0 + ty + j) * C + c0 + tx];
    __syncthreads();
    #pragma unroll
    for (int j = 0; j < 32; j += 8) {
        float v = t[tx][ty + j];                 // = S[r0+tx][c0+ty+j]
        unsigned short h, l;
        bsplit(v, h, l);
        size_t o = (size_t)(c0 + ty + j) * R + r0 + tx;
        H[o] = *(__nv_bfloat16*)&h;
        L[o] = *(__nv_bfloat16*)&l;
    }
}

// ---------------- router ----------------
__global__ void k_router(const float* __restrict__ h, const float* __restrict__ rw) {
    int t = blockIdx.x;
    int lane = threadIdx.x & 31;
    int w = threadIdx.x >> 5;
    const float* hr = h + (size_t)t * Dn;
    float acc = 0.f;
    for (int d = lane; d < Dn; d += 32) acc += hr[d] * rw[d * En + w];
    #pragma unroll
    for (int o = 16; o; o >>= 1) acc += __shfl_xor_sync(0xFFFFFFFFu, acc, o);
    __shared__ float lg[En];
    if (lane == 0) lg[w] = acc;
    __syncthreads();
    if (threadIdx.x == 0) {
        float l[En];
        #pragma unroll
        for (int e = 0; e < En; e++) l[e] = lg[e];
        float m = l[0];
        #pragma unroll
        for (int e = 1; e < En; e++) m = fmaxf(m, l[e]);
        float p[En], s = 0.f;
        #pragma unroll
        for (int e = 0; e < En; e++) { p[e] = expf(l[e] - m); s += p[e]; }
        float inv = 1.0f / s;
        int i0 = 0;
        #pragma unroll
        for (int e = 1; e < En; e++) if (l[e] > l[i0]) i0 = e;
        int i1 = -1;
        #pragma unroll
        for (int e = 0; e < En; e++) {
            if (e == i0) continue;
            if (i1 < 0 || l[e] > l[i1]) i1 = e;
        }
        g_top2[2 * t] = i0;
        g_top2[2 * t + 1] = i1;
        g_topw[2 * t] = p[i0] * inv;
        g_topw[2 * t + 1] = p[i1] * inv;
        g_wkept[2 * t] = 0.f;
        g_wkept[2 * t + 1] = 0.f;
    }
}

// ---------------- capacity scan (smem-staged) ----------------
__global__ void k_scan() {
    __shared__ int s_top[Tn * 2];
    for (int i = threadIdx.x; i < Tn * 2; i += 256) s_top[i] = g_top2[i];
    __syncthreads();
    int lane = threadIdx.x & 31;
    int e = threadIdx.x >> 5;
    if (e >= En) return;
    int base = 0;
    for (int t0 = 0; t0 < Tn; t0 += 32) {
        int t = t0 + lane;
        int a = s_top[2 * t], b = s_top[2 * t + 1];
        int j = (a == e) ? 0 : ((b == e) ? 1 : -1);
        unsigned bal = __ballot_sync(0xFFFFFFFFu, j >= 0);
        int rank = base + __popc(bal & (0xFFFFFFFFu >> (31 - lane)));
        if (j >= 0 && rank <= CAPn) {
            int slot = rank - 1;
            g_elist[e * CAPn + slot] = t;
            float wv = g_topw[2 * t + j];
            g_ew[e * CAPn + slot] = wv;
            g_wkept[2 * t + j] = wv;
        }
        base += __popc(bal);
    }
    if (lane == 0) g_ecnt[e] = base < CAPn ? base : CAPn;
}

// ---------------- hout = hin * (1 - rho) ----------------
__global__ void k_scale(const float* __restrict__ hin, float* __restrict__ hout) {
    int t = blockIdx.x;
    float s = 1.0f - (g_wkept[2 * t] + g_wkept[2 * t + 1]);
    float4 v = ((const float4*)(hin + (size_t)t * Dn))[threadIdx.x];
    v.x *= s; v.y *= s; v.z *= s; v.w *= s;
    ((float4*)(hout + (size_t)t * Dn))[threadIdx.x] = v;
}

// ---------------- final rmsnorm ----------------
__global__ void k_rms(const float* __restrict__ hin, const float* __restrict__ lnw,
                      float* __restrict__ hout) {
    int t = blockIdx.x;
    int lane = threadIdx.x & 31, wid = threadIdx.x >> 5;
    float4 v = ((const float4*)(hin + (size_t)t * Dn))[threadIdx.x];
    float s = v.x * v.x + v.y * v.y + v.z * v.z + v.w * v.w;
    #pragma unroll
    for (int o = 16; o; o >>= 1) s += __shfl_xor_sync(0xFFFFFFFFu, s, o);
    __shared__ float red[8];
    if (lane == 0) red[wid] = s;
    __syncthreads();
    float tot = 0.f;
    #pragma unroll
    for (int i = 0; i < 8; i++) tot += red[i];
    float sc = rsqrtf(tot * (1.0f / Dn) + 1e-6f);
    float4 w = ((const float4*)lnw)[threadIdx.x];
    v.x *= sc * w.x; v.y *= sc * w.y; v.z *= sc * w.z; v.w *= sc * w.w;
    ((float4*)(hout + (size_t)t * Dn))[threadIdx.x] = v;
}

// ================= shared HMMA tile framework constants =================
#define ROWB 80                      // padded smem row: 32 bf16 + 8 pad
#define ARRB (128 * ROWB)
#define STAGEB (4 * ARRB)            // 40960 B

#define HMMA_PROLOG \
    extern __shared__ char smraw[]; \
    const uint32_t sbase = s2u(smraw); \
    const int tid = threadIdx.x; \
    const int lane = tid & 31; \
    const int wm = (tid >> 5) & 3; \
    const int wn = tid >> 7; \
    float acc[2][8][4]; \
    _Pragma("unroll") for (int i = 0; i < 2; i++) \
        _Pragma("unroll") for (int j = 0; j < 8; j++) \
            _Pragma("unroll") for (int q = 0; q < 4; q++) acc[i][j][q] = 0.f; \
    const int a_lr = lane & 15; \
    const int a_lc = ((lane >> 4) << 3); \
    const int b_nr = ((lane >> 4) << 3) + (lane & 7); \
    const int b_kc = (lane & 8);

#define HMMA_MAINLOOP(NCHKv) \
    load_stage(0, 0); \
    load_stage(1, 1); \
    for (int c = 0; c < (NCHKv); c++) { \
        const int st = c & 1; \
        if (c + 1 < (NCHKv)) asm volatile("cp.async.wait_group 1;" ::: "memory"); \
        else                 asm volatile("cp.async.wait_group 0;" ::: "memory"); \
        __syncthreads(); \
        const uint32_t sb = sbase + st * STAGEB; \
        _Pragma("unroll") \
        for (int k16 = 0; k16 < 32; k16 += 16) { \
            uint32_t ah[2][4], al[2][4]; \
            _Pragma("unroll") \
            for (int mi = 0; mi < 2; mi++) { \
                uint32_t aoff = (uint32_t)((wm * 32 + mi * 16 + a_lr) * ROWB + (k16 + a_lc) * 2); \
                ldsm4(ah[mi], sb + aoff); \
                ldsm4(al[mi], sb + ARRB + aoff); \
            } \
            _Pragma("unroll") \
            for (int ng = 0; ng < 4; ng++) { \
                uint32_t boff = (uint32_t)((wn * 64 + ng * 16 + b_nr) * ROWB + (k16 + b_kc) * 2); \
                uint32_t bh[4], bl[4]; \
                ldsm4(bh, sb + 2 * ARRB + boff); \
                ldsm4(bl, sb + 3 * ARRB + boff); \
                _Pragma("unroll") \
                for (int hv = 0; hv < 2; hv++) { \
                    const int nj = ng * 2 + hv; \
                    _Pragma("unroll") \
                    for (int mi = 0; mi < 2; mi++) { \
                        mma16816(acc[mi][nj], ah[mi], bh[2 * hv], bh[2 * hv + 1]); \
                        mma16816(acc[mi][nj], al[mi], bh[2 * hv], bh[2 * hv + 1]); \
                        mma16816(acc[mi][nj], ah[mi], bl[2 * hv], bl[2 * hv + 1]); \
                    } \
                } \
            } \
        } \
        __syncthreads(); \
        if (c + 2 < (NCHKv)) load_stage(c + 2, st); \
    }

// ---------------- tied projection: C = Ah.Bh + Al.Bh + Ah.Bl ----------------
__global__ __launch_bounds__(256, 1)
void k_proj_hmma(const __nv_bfloat16* __restrict__ Ah, const __nv_bfloat16* __restrict__ Al,
                 const __nv_bfloat16* __restrict__ Bh, const __nv_bfloat16* __restrict__ Bl,
                 float* __restrict__ C) {
    HMMA_PROLOG
    const int m0 = blockIdx.x * 128;
    const int n0 = blockIdx.y * 128;
    size_t gaA[2], gaB[2];
    uint32_t soff[2];
    #pragma unroll
    for (int hf = 0; hf < 2; hf++) {
        int id = tid + hf * 256;
        int row = id >> 2, seg = id & 3;
        gaA[hf] = (size_t)(m0 + row) * Dn + seg * 8;
        gaB[hf] = (size_t)(n0 + row) * Dn + seg * 8;
        soff[hf] = (uint32_t)(row * ROWB + seg * 16);
    }
    auto load_stage = [&](int c, int st) {
        const int kb = c * 32;
        const uint32_t sb = sbase + st * STAGEB;
        #pragma unroll
        for (int hf = 0; hf < 2; hf++) {
            cpa16(sb + soff[hf], Ah + gaA[hf] + kb);
            cpa16(sb + ARRB + soff[hf], Al + gaA[hf] + kb);
            cpa16(sb + 2 * ARRB + soff[hf], Bh + gaB[hf] + kb);
            cpa16(sb + 3 * ARRB + soff[hf], Bl + gaB[hf] + kb);
        }
        asm volatile("cp.async.commit_group;" ::: "memory");
    };
    HMMA_MAINLOOP(Dn / 32)
    const int g = lane >> 2, t2 = (lane & 3) << 1;
    #pragma unroll
    for (int mi = 0; mi < 2; mi++) {
        #pragma unroll
        for (int nj = 0; nj < 8; nj++) {
            int r = m0 + wm * 32 + mi * 16 + g;
            int col = n0 + wn * 64 + nj * 8 + t2;
            *(float2*)&C[(size_t)r * Vn + col] = make_float2(acc[mi][nj][0], acc[mi][nj][1]);
            *(float2*)&C[(size_t)(r + 8) * Vn + col] = make_float2(acc[mi][nj][2], acc[mi][nj][3]);
        }
    }
}

// ---------------- expert GEMM1: hid = gelu(gather(h) @ w1), split-output ----------------
__global__ __launch_bounds__(256, 1)
void k_gemm1_hmma(const __nv_bfloat16* __restrict__ Ah, const __nv_bfloat16* __restrict__ Al) {
    const int e = blockIdx.z;
    const int cnt = g_ecnt[e];
    const int m0 = blockIdx.y * 128;
    if (m0 >= cnt) return;
    HMMA_PROLOG
    const int n0 = blockIdx.x * 128;
    const __nv_bfloat16* Wh = g_w1h + (size_t)e * Fn * Dn;   // [F][D]
    const __nv_bfloat16* Wl = g_w1l + (size_t)e * Fn * Dn;
    size_t gaA[2], gaB[2];
    uint32_t soff[2];
    #pragma unroll
    for (int hf = 0; hf < 2; hf++) {
        int id = tid + hf * 256;
        int row = id >> 2, seg = id & 3;
        int mrow = m0 + row;
        if (mrow >= cnt) mrow = cnt - 1;
        int tok = g_elist[e * CAPn + mrow];
        gaA[hf] = (size_t)tok * Dn + seg * 8;
        gaB[hf] = (size_t)(n0 + row) * Dn + seg * 8;
        soff[hf] = (uint32_t)(row * ROWB + seg * 16);
    }
    auto load_stage = [&](int c, int st) {
        const int kb = c * 32;
        const uint32_t sb = sbase + st * STAGEB;
        #pragma unroll
        for (int hf = 0; hf < 2; hf++) {
            cpa16(sb + soff[hf], Ah + gaA[hf] + kb);
            cpa16(sb + ARRB + soff[hf], Al + gaA[hf] + kb);
            cpa16(sb + 2 * ARRB + soff[hf], Wh + gaB[hf] + kb);
            cpa16(sb + 3 * ARRB + soff[hf], Wl + gaB[hf] + kb);
        }
        asm volatile("cp.async.commit_group;" ::: "memory");
    };
    HMMA_MAINLOOP(Dn / 32)
    __nv_bfloat16* Hh = g_hidh + (size_t)e * CAPn * Fn;
    __nv_bfloat16* Hl = g_hidl + (size_t)e * CAPn * Fn;
    const int g = lane >> 2, t2 = (lane & 3) << 1;
    #pragma unroll
    for (int mi = 0; mi < 2; mi++) {
        int r = wm * 32 + mi * 16 + g;
        #pragma unroll
        for (int nj = 0; nj < 8; nj++) {
            int col = n0 + wn * 64 + nj * 8 + t2;
            int s0 = m0 + r, s1 = m0 + r + 8;
            if (s0 < cnt) {
                float x0 = gelu_t(acc[mi][nj][0]), x1 = gelu_t(acc[mi][nj][1]);
                unsigned short h0, l0, h1, l1;
                bsplit(x0, h0, l0);
                bsplit(x1, h1, l1);
                *(uint32_t*)&Hh[(size_t)s0 * Fn + col] = (uint32_t)h0 | ((uint32_t)h1 << 16);
                *(uint32_t*)&Hl[(size_t)s0 * Fn + col] = (uint32_t)l0 | ((uint32_t)l1 << 16);
            }
            if (s1 < cnt) {
                float x2 = gelu_t(acc[mi][nj][2]), x3 = gelu_t(acc[mi][nj][3]);
                unsigned short h2, l2, h3, l3;
                bsplit(x2, h2, l2);
                bsplit(x3, h3, l3);
                *(uint32_t*)&Hh[(size_t)s1 * Fn + col] = (uint32_t)h2 | ((uint32_t)h3 << 16);
                *(uint32_t*)&Hl[(size_t)s1 * Fn + col] = (uint32_t)l2 | ((uint32_t)l3 << 16);
            }
        }
    }
}

// ---------------- expert GEMM2: hout += w_e * (hid @ w2), atomic scatter ----------------
__global__ __launch_bounds__(256, 1)
void k_gemm2_hmma(float* __restrict__ hout) {
    const int e = blockIdx.z;
    const int cnt = g_ecnt[e];
    const int m0 = blockIdx.y * 128;
    if (m0 >= cnt) return;
    HMMA_PROLOG
    const int n0 = blockIdx.x * 128;
    const __nv_bfloat16* Ahp = g_hidh + (size_t)e * CAPn * Fn;
    const __nv_bfloat16* Alp = g_hidl + (size_t)e * CAPn * Fn;
    const __nv_bfloat16* Wh = g_w2h + (size_t)e * Dn * Fn;   // [D][F]
    const __nv_bfloat16* Wl = g_w2l + (size_t)e * Dn * Fn;
    size_t gaA[2], gaB[2];
    uint32_t soff[2];
    #pragma unroll
    for (int hf = 0; hf < 2; hf++) {
        int id = tid + hf * 256;
        int row = id >> 2, seg = id & 3;
        gaA[hf] = (size_t)(m0 + row) * Fn + seg * 8;
        gaB[hf] = (size_t)(n0 + row) * Fn + seg * 8;
        soff[hf] = (uint32_t)(row * ROWB + seg * 16);
    }
    auto load_stage = [&](int c, int st) {
        const int kb = c * 32;
        const uint32_t sb = sbase + st * STAGEB;
        #pragma unroll
        for (int hf = 0; hf < 2; hf++) {
            cpa16(sb + soff[hf], Ahp + gaA[hf] + kb);
            cpa16(sb + ARRB + soff[hf], Alp + gaA[hf] + kb);
            cpa16(sb + 2 * ARRB + soff[hf], Wh + gaB[hf] + kb);
            cpa16(sb + 3 * ARRB + soff[hf], Wl + gaB[hf] + kb);
        }
        asm volatile("cp.async.commit_group;" ::: "memory");
    };
    HMMA_MAINLOOP(Fn / 32)
    const int g = lane >> 2, t2 = (lane & 3) << 1;
    #pragma unroll
    for (int mi = 0; mi < 2; mi++) {
        int r = wm * 32 + mi * 16 + g;
        int s0 = m0 + r, s1 = m0 + r + 8;
        int tok0 = 0, tok1 = 0;
        float w0 = 0.f, w1v = 0.f;
        if (s0 < cnt) { tok0 = g_elist[e * CAPn + s0]; w0 = g_ew[e * CAPn + s0]; }
        if (s1 < cnt) { tok1 = g_elist[e * CAPn + s1]; w1v = g_ew[e * CAPn + s1]; }
        #pragma unroll
        for (int nj = 0; nj < 8; nj++) {
            int col = n0 + wn * 64 + nj * 8 + t2;
            if (s0 < cnt) {
                atomicAdd(&hout[(size_t)tok0 * Dn + col], w0 * acc[mi][nj][0]);
                atomicAdd(&hout[(size_t)tok0 * Dn + col + 1], w0 * acc[mi][nj][1]);
            }
            if (s1 < cnt) {
                atomicAdd(&hout[(size_t)tok1 * Dn + col], w1v * acc[mi][nj][2]);
                atomicAdd(&hout[(size_t)tok1 * Dn + col + 1], w1v * acc[mi][nj][3]);
            }
        }
    }
}

// ---------------- launch ----------------
extern "C" void kernel_launch(void* const* d_in, const int* in_sizes, int n_in,
                              void* d_out, int out_size) {
    (void)in_sizes; (void)n_in; (void)out_size;
    const int*   ids    = (const int*)d_in[0];
    const float* embed  = (const float*)d_in[1];
    const float* router = (const float*)d_in[2];
    const float* w1     = (const float*)d_in[3];
    const float* w2     = (const float*)d_in[4];
    const float* lnw    = (const float*)d_in[5];
    float* out = (float*)d_out;

    float *hA, *hB;
    __nv_bfloat16 *pBh, *pBl, *pAh, *pAl, *pw1h, *pw1l, *pw2h, *pw2l;
    cudaGetSymbolAddress((void**)&hA, g_hA);
    cudaGetSymbolAddress((void**)&hB, g_hB);
    cudaGetSymbolAddress((void**)&pBh, g_Bh);
    cudaGetSymbolAddress((void**)&pBl, g_Bl);
    cudaGetSymbolAddress((void**)&pAh, g_Ah);
    cudaGetSymbolAddress((void**)&pAl, g_Al);
    cudaGetSymbolAddress((void**)&pw1h, g_w1h);
    cudaGetSymbolAddress((void**)&pw1l, g_w1l);
    cudaGetSymbolAddress((void**)&pw2h, g_w2h);
    cudaGetSymbolAddress((void**)&pw2l, g_w2l);

    static bool attr_done = false;
    if (!attr_done) {
        cudaFuncSetAttribute(k_proj_hmma, cudaFuncAttributeMaxDynamicSharedMemorySize, 2 * STAGEB);
        cudaFuncSetAttribute(k_gemm1_hmma, cudaFuncAttributeMaxDynamicSharedMemorySize, 2 * STAGEB);
        cudaFuncSetAttribute(k_gemm2_hmma, cudaFuncAttributeMaxDynamicSharedMemorySize, 2 * STAGEB);
        attr_done = true;
    }

    // one-time-per-launch weight prep (deterministic, same every call)
    k_split<<<(Vn * Dn / 4 + 255) / 256, 256>>>(embed, pBh, pBl, Vn * Dn / 4);
    k_tsplit<<<dim3(Fn / 32, Dn / 32, En), dim3(32, 8)>>>(w1, pw1h, pw1l, Dn, Fn);
    k_tsplit<<<dim3(Dn / 32, Fn / 32, En), dim3(32, 8)>>>(w2, pw2h, pw2l, Fn, Dn);

    k_embed<<<(Tn * Dn / 4) / 256, 256>>>(ids, embed);

    float* hin = hA;
    float* hout = hB;
    for (int hop = 0; hop < 2; hop++) {
        k_router<<<Tn, 256>>>(hin, router + (size_t)hop * Dn * En);
        k_scan<<<1, 256>>>();
        k_split<<<(Tn * Dn / 4 + 255) / 256, 256>>>(hin, pAh, pAl, Tn * Dn / 4);
        k_scale<<<Tn, 256>>>(hin, hout);
        k_gemm1_hmma<<<dim3(Fn / 128, (CAPn + 127) / 128, En), 256, 2 * STAGEB>>>(pAh, pAl);
        k_gemm2_hmma<<<dim3(Dn / 128, (CAPn + 127) / 128, En), 256, 2 * STAGEB>>>(hout);
        float* tmp = hin; hin = hout; hout = tmp;
    }
    k_rms<<<Tn, 256>>>(hin, lnw, hout);
    k_split<<<(Tn * Dn / 4 + 255) / 256, 256>>>(hout, pAh, pAl, Tn * Dn / 4);

    k_proj_hmma<<<dim3(Tn / 128, Vn / 128), 256, 2 * STAGEB>>>(pAh, pAl, pBh, pBl, out);
}

// round 6
// speedup vs baseline: 4.1429x; 1.8685x over previous
#include <cuda_runtime.h>
#include <cuda_bf16.h>
#include <cuda_fp16.h>
#include <math.h>
#include <stdint.h>

#define Tn 2048
#define Dn 1024
#define En 8
#define Fn 2048
#define Vn 32000
#define CAPn 640

// ---------------- device scratch (no allocations allowed) ----------------
__device__ float g_hA[Tn * Dn];
__device__ float g_hB[Tn * Dn];
__device__ int   g_top2[Tn * 2];
__device__ float g_topw[Tn * 2];
__device__ float g_wkept[Tn * 2];
__device__ int   g_elist[En * CAPn];
__device__ float g_ew[En * CAPn];
__device__ int   g_ecnt[En];
__device__ __half g_Bp[(size_t)Vn * Dn];                 // embed fp16 (proj B)
__device__ __nv_bfloat16 g_Ah[Tn * Dn];                  // h split hi (router-safe path)
__device__ __nv_bfloat16 g_Al[Tn * Dn];                  // h split lo
__device__ __half g_Ap[Tn * Dn];                         // h fp16 (terminal path)
__device__ __nv_bfloat16 g_w1h[(size_t)En * Fn * Dn];    // w1^T hi [E][F][D]
__device__ __nv_bfloat16 g_w1l[(size_t)En * Fn * Dn];
__device__ __half        g_w1p[(size_t)En * Fn * Dn];    // w1^T fp16
__device__ __nv_bfloat16 g_w2h[(size_t)En * Dn * Fn];    // w2^T hi [E][D][F]
__device__ __nv_bfloat16 g_w2l[(size_t)En * Dn * Fn];
__device__ __half        g_w2p[(size_t)En * Dn * Fn];    // w2^T fp16
__device__ __nv_bfloat16 g_hidh[(size_t)En * CAPn * Fn]; // hop-1 hid split hi
__device__ __nv_bfloat16 g_hidl[(size_t)En * CAPn * Fn];
__device__ __half        g_hidp[(size_t)En * CAPn * Fn]; // hop-2 hid fp16

__device__ __forceinline__ float gelu_t(float x) {
    float u = 0.7978845608028654f * (x + 0.044715f * x * x * x);
    return 0.5f * x * (1.0f + tanhf(u));
}

// ---------------- hmma helpers ----------------
__device__ __forceinline__ uint32_t s2u(const void* p) {
    uint32_t a;
    asm("{ .reg .u64 t; cvta.to.shared.u64 t, %1; cvt.u32.u64 %0, t; }" : "=r"(a) : "l"(p));
    return a;
}
__device__ __forceinline__ void ldsm4(uint32_t* r, uint32_t a) {
    asm volatile("ldmatrix.sync.aligned.m8n8.x4.shared.b16 {%0,%1,%2,%3}, [%4];"
                 : "=r"(r[0]), "=r"(r[1]), "=r"(r[2]), "=r"(r[3]) : "r"(a));
}
__device__ __forceinline__ void mma16816(float* c, const uint32_t* a, uint32_t b0, uint32_t b1) {
    asm volatile("mma.sync.aligned.m16n8k16.row.col.f32.bf16.bf16.f32 "
                 "{%0,%1,%2,%3}, {%4,%5,%6,%7}, {%8,%9}, {%0,%1,%2,%3};"
                 : "+f"(c[0]), "+f"(c[1]), "+f"(c[2]), "+f"(c[3])
                 : "r"(a[0]), "r"(a[1]), "r"(a[2]), "r"(a[3]), "r"(b0), "r"(b1));
}
__device__ __forceinline__ void mma16816h(float* c, const uint32_t* a, uint32_t b0, uint32_t b1) {
    asm volatile("mma.sync.aligned.m16n8k16.row.col.f32.f16.f16.f32 "
                 "{%0,%1,%2,%3}, {%4,%5,%6,%7}, {%8,%9}, {%0,%1,%2,%3};"
                 : "+f"(c[0]), "+f"(c[1]), "+f"(c[2]), "+f"(c[3])
                 : "r"(a[0]), "r"(a[1]), "r"(a[2]), "r"(a[3]), "r"(b0), "r"(b1));
}
__device__ __forceinline__ void cpa16(uint32_t dst, const void* src) {
    asm volatile("cp.async.cg.shared.global [%0], [%1], 16;" :: "r"(dst), "l"(src) : "memory");
}
__device__ __forceinline__ void bsplit(float x, unsigned short& h, unsigned short& l) {
    __nv_bfloat16 hb = __float2bfloat16_rn(x);
    __nv_bfloat16 lb = __float2bfloat16_rn(x - __bfloat162float(hb));
    h = *(unsigned short*)&hb;
    l = *(unsigned short*)&lb;
}

// ---------------- embedding gather ----------------
__global__ void k_embed(const int* __restrict__ ids, const float* __restrict__ ew) {
    int i = blockIdx.x * blockDim.x + threadIdx.x;
    int t = i / (Dn / 4);
    int d4 = i % (Dn / 4);
    float4 v = ((const float4*)(ew + (size_t)ids[t] * Dn))[d4];
    ((float4*)(g_hA + (size_t)t * Dn))[d4] = v;
}

// ---------------- fp32 -> fp16 convert ----------------
__global__ void k_cvt16(const float* __restrict__ src, __half* __restrict__ dst, int n4) {
    int i = blockIdx.x * blockDim.x + threadIdx.x;
    if (i >= n4) return;
    float4 v = ((const float4*)src)[i];
    __half2 a = __floats2half2_rn(v.x, v.y);
    __half2 b = __floats2half2_rn(v.z, v.w);
    ((uint2*)dst)[i] = make_uint2(*(uint32_t*)&a, *(uint32_t*)&b);
}

// ---------------- fp32 -> bf16 hi/lo + fp16 ----------------
__global__ void k_split3(const float* __restrict__ src, __nv_bfloat16* __restrict__ hi,
                         __nv_bfloat16* __restrict__ lo, __half* __restrict__ fp, int n4) {
    int i = blockIdx.x * blockDim.x + threadIdx.x;
    if (i >= n4) return;
    float4 v = ((const float4*)src)[i];
    float x[4] = {v.x, v.y, v.z, v.w};
    unsigned short h[4], l[4];
    #pragma unroll
    for (int j = 0; j < 4; j++) bsplit(x[j], h[j], l[j]);
    ((uint2*)hi)[i] = make_uint2((uint32_t)h[0] | ((uint32_t)h[1] << 16),
                                 (uint32_t)h[2] | ((uint32_t)h[3] << 16));
    ((uint2*)lo)[i] = make_uint2((uint32_t)l[0] | ((uint32_t)l[1] << 16),
                                 (uint32_t)l[2] | ((uint32_t)l[3] << 16));
    __half2 a = __floats2half2_rn(v.x, v.y);
    __half2 b = __floats2half2_rn(v.z, v.w);
    ((uint2*)fp)[i] = make_uint2(*(uint32_t*)&a, *(uint32_t*)&b);
}

// ---------------- transpose+split: [E][R][C] fp32 -> [E][C][R] bf16 hi/lo + fp16 ----------------
__global__ void k_tsplit3(const float* __restrict__ src, __nv_bfloat16* __restrict__ hi,
                          __nv_bfloat16* __restrict__ lo, __half* __restrict__ fp,
                          int R, int C) {
    __shared__ float t[32][33];
    int e = blockIdx.z;
    const float* S = src + (size_t)e * R * C;
    __nv_bfloat16* H = hi + (size_t)e * R * C;
    __nv_bfloat16* L = lo + (size_t)e * R * C;
    __half* P = fp + (size_t)e * R * C;
    int c0 = blockIdx.x * 32, r0 = blockIdx.y * 32;
    int tx = threadIdx.x, ty = threadIdx.y;
    #pragma unroll
    for (int j = 0; j < 32; j += 8)
        t[ty + j][tx] = S[(size_t)(r0 + ty + j) * C + c0 + tx];
    __syncthreads();
    #pragma unroll
    for (int j = 0; j < 32; j += 8) {
        float v = t[tx][ty + j];
        unsigned short h, l;
        bsplit(v, h, l);
        size_t o = (size_t)(c0 + ty + j) * R + r0 + tx;
        H[o] = *(__nv_bfloat16*)&h;
        L[o] = *(__nv_bfloat16*)&l;
        P[o] = __float2half_rn(v);
    }
}

// ---------------- router ----------------
__global__ void k_router(const float* __restrict__ h, const float* __restrict__ rw) {
    int t = blockIdx.x;
    int lane = threadIdx.x & 31;
    int w = threadIdx.x >> 5;
    const float* hr = h + (size_t)t * Dn;
    float acc = 0.f;
    for (int d = lane; d < Dn; d += 32) acc += hr[d] * rw[d * En + w];
    #pragma unroll
    for (int o = 16; o; o >>= 1) acc += __shfl_xor_sync(0xFFFFFFFFu, acc, o);
    __shared__ float lg[En];
    if (lane == 0) lg[w] = acc;
    __syncthreads();
    if (threadIdx.x == 0) {
        float l[En];
        #pragma unroll
        for (int e = 0; e < En; e++) l[e] = lg[e];
        float m = l[0];
        #pragma unroll
        for (int e = 1; e < En; e++) m = fmaxf(m, l[e]);
        float p[En], s = 0.f;
        #pragma unroll
        for (int e = 0; e < En; e++) { p[e] = expf(l[e] - m); s += p[e]; }
        float inv = 1.0f / s;
        int i0 = 0;
        #pragma unroll
        for (int e = 1; e < En; e++) if (l[e] > l[i0]) i0 = e;
        int i1 = -1;
        #pragma unroll
        for (int e = 0; e < En; e++) {
            if (e == i0) continue;
            if (i1 < 0 || l[e] > l[i1]) i1 = e;
        }
        g_top2[2 * t] = i0;
        g_top2[2 * t + 1] = i1;
        g_topw[2 * t] = p[i0] * inv;
        g_topw[2 * t + 1] = p[i1] * inv;
        g_wkept[2 * t] = 0.f;
        g_wkept[2 * t + 1] = 0.f;
    }
}

// ---------------- capacity scan (smem-staged) ----------------
__global__ void k_scan() {
    __shared__ int s_top[Tn * 2];
    for (int i = threadIdx.x; i < Tn * 2; i += 256) s_top[i] = g_top2[i];
    __syncthreads();
    int lane = threadIdx.x & 31;
    int e = threadIdx.x >> 5;
    if (e >= En) return;
    int base = 0;
    for (int t0 = 0; t0 < Tn; t0 += 32) {
        int t = t0 + lane;
        int a = s_top[2 * t], b = s_top[2 * t + 1];
        int j = (a == e) ? 0 : ((b == e) ? 1 : -1);
        unsigned bal = __ballot_sync(0xFFFFFFFFu, j >= 0);
        int rank = base + __popc(bal & (0xFFFFFFFFu >> (31 - lane)));
        if (j >= 0 && rank <= CAPn) {
            int slot = rank - 1;
            g_elist[e * CAPn + slot] = t;
            float wv = g_topw[2 * t + j];
            g_ew[e * CAPn + slot] = wv;
            g_wkept[2 * t + j] = wv;
        }
        base += __popc(bal);
    }
    if (lane == 0) g_ecnt[e] = base < CAPn ? base : CAPn;
}

// ---------------- hout = hin * (1 - rho) ----------------
__global__ void k_scale(const float* __restrict__ hin, float* __restrict__ hout) {
    int t = blockIdx.x;
    float s = 1.0f - (g_wkept[2 * t] + g_wkept[2 * t + 1]);
    float4 v = ((const float4*)(hin + (size_t)t * Dn))[threadIdx.x];
    v.x *= s; v.y *= s; v.z *= s; v.w *= s;
    ((float4*)(hout + (size_t)t * Dn))[threadIdx.x] = v;
}

// ---------------- final rmsnorm ----------------
__global__ void k_rms(const float* __restrict__ hin, const float* __restrict__ lnw,
                      float* __restrict__ hout) {
    int t = blockIdx.x;
    int lane = threadIdx.x & 31, wid = threadIdx.x >> 5;
    float4 v = ((const float4*)(hin + (size_t)t * Dn))[threadIdx.x];
    float s = v.x * v.x + v.y * v.y + v.z * v.z + v.w * v.w;
    #pragma unroll
    for (int o = 16; o; o >>= 1) s += __shfl_xor_sync(0xFFFFFFFFu, s, o);
    __shared__ float red[8];
    if (lane == 0) red[wid] = s;
    __syncthreads();
    float tot = 0.f;
    #pragma unroll
    for (int i = 0; i < 8; i++) tot += red[i];
    float sc = rsqrtf(tot * (1.0f / Dn) + 1e-6f);
    float4 w = ((const float4*)lnw)[threadIdx.x];
    v.x *= sc * w.x; v.y *= sc * w.y; v.z *= sc * w.z; v.w *= sc * w.w;
    ((float4*)(hout + (size_t)t * Dn))[threadIdx.x] = v;
}

// ================= HMMA tile framework =================
#define ROWB 80
#define ARRB (128 * ROWB)
#define STAGEB (4 * ARRB)            // bf16 3-term: 4 operand tiles
#define STAGE2B (2 * ARRB)           // fp16 single: 2 operand tiles

#define HMMA_PROLOG \
    extern __shared__ char smraw[]; \
    const uint32_t sbase = s2u(smraw); \
    const int tid = threadIdx.x; \
    const int lane = tid & 31; \
    const int wm = (tid >> 5) & 3; \
    const int wn = tid >> 7; \
    float acc[2][8][4]; \
    _Pragma("unroll") for (int i = 0; i < 2; i++) \
        _Pragma("unroll") for (int j = 0; j < 8; j++) \
            _Pragma("unroll") for (int q = 0; q < 4; q++) acc[i][j][q] = 0.f; \
    const int a_lr = lane & 15; \
    const int a_lc = ((lane >> 4) << 3); \
    const int b_nr = ((lane >> 4) << 3) + (lane & 7); \
    const int b_kc = (lane & 8);

// 3-term bf16 mainloop (4 tiles/stage)
#define HMMA_MAINLOOP(NCHKv) \
    load_stage(0, 0); \
    load_stage(1, 1); \
    for (int c = 0; c < (NCHKv); c++) { \
        const int st = c & 1; \
        if (c + 1 < (NCHKv)) asm volatile("cp.async.wait_group 1;" ::: "memory"); \
        else                 asm volatile("cp.async.wait_group 0;" ::: "memory"); \
        __syncthreads(); \
        const uint32_t sb = sbase + st * STAGEB; \
        _Pragma("unroll") \
        for (int k16 = 0; k16 < 32; k16 += 16) { \
            uint32_t ah[2][4], al[2][4]; \
            _Pragma("unroll") \
            for (int mi = 0; mi < 2; mi++) { \
                uint32_t aoff = (uint32_t)((wm * 32 + mi * 16 + a_lr) * ROWB + (k16 + a_lc) * 2); \
                ldsm4(ah[mi], sb + aoff); \
                ldsm4(al[mi], sb + ARRB + aoff); \
            } \
            _Pragma("unroll") \
            for (int ng = 0; ng < 4; ng++) { \
                uint32_t boff = (uint32_t)((wn * 64 + ng * 16 + b_nr) * ROWB + (k16 + b_kc) * 2); \
                uint32_t bh[4], bl[4]; \
                ldsm4(bh, sb + 2 * ARRB + boff); \
                ldsm4(bl, sb + 3 * ARRB + boff); \
                _Pragma("unroll") \
                for (int hv = 0; hv < 2; hv++) { \
                    const int nj = ng * 2 + hv; \
                    _Pragma("unroll") \
                    for (int mi = 0; mi < 2; mi++) { \
                        mma16816(acc[mi][nj], ah[mi], bh[2 * hv], bh[2 * hv + 1]); \
                        mma16816(acc[mi][nj], al[mi], bh[2 * hv], bh[2 * hv + 1]); \
                        mma16816(acc[mi][nj], ah[mi], bl[2 * hv], bl[2 * hv + 1]); \
                    } \
                } \
            } \
        } \
        __syncthreads(); \
        if (c + 2 < (NCHKv)) load_stage(c + 2, st); \
    }

// single-pass fp16 mainloop (2 tiles/stage)
#define HMMA16_MAINLOOP(NCHKv) \
    load_stage(0, 0); \
    load_stage(1, 1); \
    for (int c = 0; c < (NCHKv); c++) { \
        const int st = c & 1; \
        if (c + 1 < (NCHKv)) asm volatile("cp.async.wait_group 1;" ::: "memory"); \
        else                 asm volatile("cp.async.wait_group 0;" ::: "memory"); \
        __syncthreads(); \
        const uint32_t sb = sbase + st * STAGE2B; \
        _Pragma("unroll") \
        for (int k16 = 0; k16 < 32; k16 += 16) { \
            uint32_t af[2][4]; \
            _Pragma("unroll") \
            for (int mi = 0; mi < 2; mi++) { \
                uint32_t aoff = (uint32_t)((wm * 32 + mi * 16 + a_lr) * ROWB + (k16 + a_lc) * 2); \
                ldsm4(af[mi], sb + aoff); \
            } \
            _Pragma("unroll") \
            for (int ng = 0; ng < 4; ng++) { \
                uint32_t boff = (uint32_t)((wn * 64 + ng * 16 + b_nr) * ROWB + (k16 + b_kc) * 2); \
                uint32_t bf[4]; \
                ldsm4(bf, sb + ARRB + boff); \
                _Pragma("unroll") \
                for (int hv = 0; hv < 2; hv++) { \
                    const int nj = ng * 2 + hv; \
                    _Pragma("unroll") \
                    for (int mi = 0; mi < 2; mi++) \
                        mma16816h(acc[mi][nj], af[mi], bf[2 * hv], bf[2 * hv + 1]); \
                } \
            } \
        } \
        __syncthreads(); \
        if (c + 2 < (NCHKv)) load_stage(c + 2, st); \
    }

// ---------------- hop-1 GEMM1 (bf16 3-term): hid = gelu(gather(h) @ w1) ----------------
__global__ __launch_bounds__(256, 1)
void k_gemm1_hmma(const __nv_bfloat16* __restrict__ Ah, const __nv_bfloat16* __restrict__ Al) {
    const int e = blockIdx.z;
    const int cnt = g_ecnt[e];
    const int m0 = blockIdx.y * 128;
    if (m0 >= cnt) return;
    HMMA_PROLOG
    const int n0 = blockIdx.x * 128;
    const __nv_bfloat16* Wh = g_w1h + (size_t)e * Fn * Dn;
    const __nv_bfloat16* Wl = g_w1l + (size_t)e * Fn * Dn;
    size_t gaA[2], gaB[2];
    uint32_t soff[2];
    #pragma unroll
    for (int hf = 0; hf < 2; hf++) {
        int id = tid + hf * 256;
        int row = id >> 2, seg = id & 3;
        int mrow = m0 + row;
        if (mrow >= cnt) mrow = cnt - 1;
        int tok = g_elist[e * CAPn + mrow];
        gaA[hf] = (size_t)tok * Dn + seg * 8;
        gaB[hf] = (size_t)(n0 + row) * Dn + seg * 8;
        soff[hf] = (uint32_t)(row * ROWB + seg * 16);
    }
    auto load_stage = [&](int c, int st) {
        const int kb = c * 32;
        const uint32_t sb = sbase + st * STAGEB;
        #pragma unroll
        for (int hf = 0; hf < 2; hf++) {
            cpa16(sb + soff[hf], Ah + gaA[hf] + kb);
            cpa16(sb + ARRB + soff[hf], Al + gaA[hf] + kb);
            cpa16(sb + 2 * ARRB + soff[hf], Wh + gaB[hf] + kb);
            cpa16(sb + 3 * ARRB + soff[hf], Wl + gaB[hf] + kb);
        }
        asm volatile("cp.async.commit_group;" ::: "memory");
    };
    HMMA_MAINLOOP(Dn / 32)
    __nv_bfloat16* Hh = g_hidh + (size_t)e * CAPn * Fn;
    __nv_bfloat16* Hl = g_hidl + (size_t)e * CAPn * Fn;
    const int g = lane >> 2, t2 = (lane & 3) << 1;
    #pragma unroll
    for (int mi = 0; mi < 2; mi++) {
        int r = wm * 32 + mi * 16 + g;
        #pragma unroll
        for (int nj = 0; nj < 8; nj++) {
            int col = n0 + wn * 64 + nj * 8 + t2;
            int s0 = m0 + r, s1 = m0 + r + 8;
            if (s0 < cnt) {
                float x0 = gelu_t(acc[mi][nj][0]), x1 = gelu_t(acc[mi][nj][1]);
                unsigned short h0, l0, h1, l1;
                bsplit(x0, h0, l0);
                bsplit(x1, h1, l1);
                *(uint32_t*)&Hh[(size_t)s0 * Fn + col] = (uint32_t)h0 | ((uint32_t)h1 << 16);
                *(uint32_t*)&Hl[(size_t)s0 * Fn + col] = (uint32_t)l0 | ((uint32_t)l1 << 16);
            }
            if (s1 < cnt) {
                float x2 = gelu_t(acc[mi][nj][2]), x3 = gelu_t(acc[mi][nj][3]);
                unsigned short h2, l2, h3, l3;
                bsplit(x2, h2, l2);
                bsplit(x3, h3, l3);
                *(uint32_t*)&Hh[(size_t)s1 * Fn + col] = (uint32_t)h2 | ((uint32_t)h3 << 16);
                *(uint32_t*)&Hl[(size_t)s1 * Fn + col] = (uint32_t)l2 | ((uint32_t)l3 << 16);
            }
        }
    }
}

// ---------------- hop-1 GEMM2 (bf16 3-term): scatter ----------------
__global__ __launch_bounds__(256, 1)
void k_gemm2_hmma(float* __restrict__ hout) {
    const int e = blockIdx.z;
    const int cnt = g_ecnt[e];
    const int m0 = blockIdx.y * 128;
    if (m0 >= cnt) return;
    HMMA_PROLOG
    const int n0 = blockIdx.x * 128;
    const __nv_bfloat16* Ahp = g_hidh + (size_t)e * CAPn * Fn;
    const __nv_bfloat16* Alp = g_hidl + (size_t)e * CAPn * Fn;
    const __nv_bfloat16* Wh = g_w2h + (size_t)e * Dn * Fn;
    const __nv_bfloat16* Wl = g_w2l + (size_t)e * Dn * Fn;
    size_t gaA[2], gaB[2];
    uint32_t soff[2];
    #pragma unroll
    for (int hf = 0; hf < 2; hf++) {
        int id = tid + hf * 256;
        int row = id >> 2, seg = id & 3;
        gaA[hf] = (size_t)(m0 + row) * Fn + seg * 8;
        gaB[hf] = (size_t)(n0 + row) * Fn + seg * 8;
        soff[hf] = (uint32_t)(row * ROWB + seg * 16);
    }
    auto load_stage = [&](int c, int st) {
        const int kb = c * 32;
        const uint32_t sb = sbase + st * STAGEB;
        #pragma unroll
        for (int hf = 0; hf < 2; hf++) {
            cpa16(sb + soff[hf], Ahp + gaA[hf] + kb);
            cpa16(sb + ARRB + soff[hf], Alp + gaA[hf] + kb);
            cpa16(sb + 2 * ARRB + soff[hf], Wh + gaB[hf] + kb);
            cpa16(sb + 3 * ARRB + soff[hf], Wl + gaB[hf] + kb);
        }
        asm volatile("cp.async.commit_group;" ::: "memory");
    };
    HMMA_MAINLOOP(Fn / 32)
    const int g = lane >> 2, t2 = (lane & 3) << 1;
    #pragma unroll
    for (int mi = 0; mi < 2; mi++) {
        int r = wm * 32 + mi * 16 + g;
        int s0 = m0 + r, s1 = m0 + r + 8;
        int tok0 = 0, tok1 = 0;
        float w0 = 0.f, w1v = 0.f;
        if (s0 < cnt) { tok0 = g_elist[e * CAPn + s0]; w0 = g_ew[e * CAPn + s0]; }
        if (s1 < cnt) { tok1 = g_elist[e * CAPn + s1]; w1v = g_ew[e * CAPn + s1]; }
        #pragma unroll
        for (int nj = 0; nj < 8; nj++) {
            int col = n0 + wn * 64 + nj * 8 + t2;
            if (s0 < cnt) {
                atomicAdd(&hout[(size_t)tok0 * Dn + col], w0 * acc[mi][nj][0]);
                atomicAdd(&hout[(size_t)tok0 * Dn + col + 1], w0 * acc[mi][nj][1]);
            }
            if (s1 < cnt) {
                atomicAdd(&hout[(size_t)tok1 * Dn + col], w1v * acc[mi][nj][2]);
                atomicAdd(&hout[(size_t)tok1 * Dn + col + 1], w1v * acc[mi][nj][3]);
            }
        }
    }
}

// ---------------- hop-2 GEMM1 (fp16 single): hidp = gelu(gather(h) @ w1) ----------------
__global__ __launch_bounds__(256, 2)
void k_gemm1_fp16(const __half* __restrict__ Ap) {
    const int e = blockIdx.z;
    const int cnt = g_ecnt[e];
    const int m0 = blockIdx.y * 128;
    if (m0 >= cnt) return;
    HMMA_PROLOG
    const int n0 = blockIdx.x * 128;
    const __half* Wp = g_w1p + (size_t)e * Fn * Dn;
    size_t gaA[2], gaB[2];
    uint32_t soff[2];
    #pragma unroll
    for (int hf = 0; hf < 2; hf++) {
        int id = tid + hf * 256;
        int row = id >> 2, seg = id & 3;
        int mrow = m0 + row;
        if (mrow >= cnt) mrow = cnt - 1;
        int tok = g_elist[e * CAPn + mrow];
        gaA[hf] = (size_t)tok * Dn + seg * 8;
        gaB[hf] = (size_t)(n0 + row) * Dn + seg * 8;
        soff[hf] = (uint32_t)(row * ROWB + seg * 16);
    }
    auto load_stage = [&](int c, int st) {
        const int kb = c * 32;
        const uint32_t sb = sbase + st * STAGE2B;
        #pragma unroll
        for (int hf = 0; hf < 2; hf++) {
            cpa16(sb + soff[hf], Ap + gaA[hf] + kb);
            cpa16(sb + ARRB + soff[hf], Wp + gaB[hf] + kb);
        }
        asm volatile("cp.async.commit_group;" ::: "memory");
    };
    HMMA16_MAINLOOP(Dn / 32)
    __half* Hp = g_hidp + (size_t)e * CAPn * Fn;
    const int g = lane >> 2, t2 = (lane & 3) << 1;
    #pragma unroll
    for (int mi = 0; mi < 2; mi++) {
        int r = wm * 32 + mi * 16 + g;
        #pragma unroll
        for (int nj = 0; nj < 8; nj++) {
            int col = n0 + wn * 64 + nj * 8 + t2;
            int s0 = m0 + r, s1 = m0 + r + 8;
            if (s0 < cnt) {
                __half2 p = __floats2half2_rn(gelu_t(acc[mi][nj][0]), gelu_t(acc[mi][nj][1]));
                *(uint32_t*)&Hp[(size_t)s0 * Fn + col] = *(uint32_t*)&p;
            }
            if (s1 < cnt) {
                __half2 p = __floats2half2_rn(gelu_t(acc[mi][nj][2]), gelu_t(acc[mi][nj][3]));
                *(uint32_t*)&Hp[(size_t)s1 * Fn + col] = *(uint32_t*)&p;
            }
        }
    }
}

// ---------------- hop-2 GEMM2 (fp16 single): scatter ----------------
__global__ __launch_bounds__(256, 2)
void k_gemm2_fp16(float* __restrict__ hout) {
    const int e = blockIdx.z;
    const int cnt = g_ecnt[e];
    const int m0 = blockIdx.y * 128;
    if (m0 >= cnt) return;
    HMMA_PROLOG
    const int n0 = blockIdx.x * 128;
    const __half* Apx = g_hidp + (size_t)e * CAPn * Fn;
    const __half* Wp = g_w2p + (size_t)e * Dn * Fn;
    size_t gaA[2], gaB[2];
    uint32_t soff[2];
    #pragma unroll
    for (int hf = 0; hf < 2; hf++) {
        int id = tid + hf * 256;
        int row = id >> 2, seg = id & 3;
        gaA[hf] = (size_t)(m0 + row) * Fn + seg * 8;
        gaB[hf] = (size_t)(n0 + row) * Fn + seg * 8;
        soff[hf] = (uint32_t)(row * ROWB + seg * 16);
    }
    auto load_stage = [&](int c, int st) {
        const int kb = c * 32;
        const uint32_t sb = sbase + st * STAGE2B;
        #pragma unroll
        for (int hf = 0; hf < 2; hf++) {
            cpa16(sb + soff[hf], Apx + gaA[hf] + kb);
            cpa16(sb + ARRB + soff[hf], Wp + gaB[hf] + kb);
        }
        asm volatile("cp.async.commit_group;" ::: "memory");
    };
    HMMA16_MAINLOOP(Fn / 32)
    const int g = lane >> 2, t2 = (lane & 3) << 1;
    #pragma unroll
    for (int mi = 0; mi < 2; mi++) {
        int r = wm * 32 + mi * 16 + g;
        int s0 = m0 + r, s1 = m0 + r + 8;
        int tok0 = 0, tok1 = 0;
        float w0 = 0.f, w1v = 0.f;
        if (s0 < cnt) { tok0 = g_elist[e * CAPn + s0]; w0 = g_ew[e * CAPn + s0]; }
        if (s1 < cnt) { tok1 = g_elist[e * CAPn + s1]; w1v = g_ew[e * CAPn + s1]; }
        #pragma unroll
        for (int nj = 0; nj < 8; nj++) {
            int col = n0 + wn * 64 + nj * 8 + t2;
            if (s0 < cnt) {
                atomicAdd(&hout[(size_t)tok0 * Dn + col], w0 * acc[mi][nj][0]);
                atomicAdd(&hout[(size_t)tok0 * Dn + col + 1], w0 * acc[mi][nj][1]);
            }
            if (s1 < cnt) {
                atomicAdd(&hout[(size_t)tok1 * Dn + col], w1v * acc[mi][nj][2]);
                atomicAdd(&hout[(size_t)tok1 * Dn + col + 1], w1v * acc[mi][nj][3]);
            }
        }
    }
}

// ---------------- tied projection (fp16 single): C = Ap . Bp^T ----------------
__global__ __launch_bounds__(256, 2)
void k_proj_fp16(const __half* __restrict__ Ap, const __half* __restrict__ Bp,
                 float* __restrict__ C) {
    HMMA_PROLOG
    const int m0 = blockIdx.x * 128;
    const int n0 = blockIdx.y * 128;
    size_t gaA[2], gaB[2];
    uint32_t soff[2];
    #pragma unroll
    for (int hf = 0; hf < 2; hf++) {
        int id = tid + hf * 256;
        int row = id >> 2, seg = id & 3;
        gaA[hf] = (size_t)(m0 + row) * Dn + seg * 8;
        gaB[hf] = (size_t)(n0 + row) * Dn + seg * 8;
        soff[hf] = (uint32_t)(row * ROWB + seg * 16);
    }
    auto load_stage = [&](int c, int st) {
        const int kb = c * 32;
        const uint32_t sb = sbase + st * STAGE2B;
        #pragma unroll
        for (int hf = 0; hf < 2; hf++) {
            cpa16(sb + soff[hf], Ap + gaA[hf] + kb);
            cpa16(sb + ARRB + soff[hf], Bp + gaB[hf] + kb);
        }
        asm volatile("cp.async.commit_group;" ::: "memory");
    };
    HMMA16_MAINLOOP(Dn / 32)
    const int g = lane >> 2, t2 = (lane & 3) << 1;
    #pragma unroll
    for (int mi = 0; mi < 2; mi++) {
        #pragma unroll
        for (int nj = 0; nj < 8; nj++) {
            int r = m0 + wm * 32 + mi * 16 + g;
            int col = n0 + wn * 64 + nj * 8 + t2;
            *(float2*)&C[(size_t)r * Vn + col] = make_float2(acc[mi][nj][0], acc[mi][nj][1]);
            *(float2*)&C[(size_t)(r + 8) * Vn + col] = make_float2(acc[mi][nj][2], acc[mi][nj][3]);
        }
    }
}

// ---------------- launch ----------------
extern "C" void kernel_launch(void* const* d_in, const int* in_sizes, int n_in,
                              void* d_out, int out_size) {
    (void)in_sizes; (void)n_in; (void)out_size;
    const int*   ids    = (const int*)d_in[0];
    const float* embed  = (const float*)d_in[1];
    const float* router = (const float*)d_in[2];
    const float* w1     = (const float*)d_in[3];
    const float* w2     = (const float*)d_in[4];
    const float* lnw    = (const float*)d_in[5];
    float* out = (float*)d_out;

    float *hA, *hB;
    __half *pBp, *pAp, *pw1p, *pw2p;
    __nv_bfloat16 *pAh, *pAl, *pw1h, *pw1l, *pw2h, *pw2l;
    cudaGetSymbolAddress((void**)&hA, g_hA);
    cudaGetSymbolAddress((void**)&hB, g_hB);
    cudaGetSymbolAddress((void**)&pBp, g_Bp);
    cudaGetSymbolAddress((void**)&pAh, g_Ah);
    cudaGetSymbolAddress((void**)&pAl, g_Al);
    cudaGetSymbolAddress((void**)&pAp, g_Ap);
    cudaGetSymbolAddress((void**)&pw1h, g_w1h);
    cudaGetSymbolAddress((void**)&pw1l, g_w1l);
    cudaGetSymbolAddress((void**)&pw1p, g_w1p);
    cudaGetSymbolAddress((void**)&pw2h, g_w2h);
    cudaGetSymbolAddress((void**)&pw2l, g_w2l);
    cudaGetSymbolAddress((void**)&pw2p, g_w2p);

    static bool attr_done = false;
    if (!attr_done) {
        cudaFuncSetAttribute(k_gemm1_hmma, cudaFuncAttributeMaxDynamicSharedMemorySize, 2 * STAGEB);
        cudaFuncSetAttribute(k_gemm2_hmma, cudaFuncAttributeMaxDynamicSharedMemorySize, 2 * STAGEB);
        cudaFuncSetAttribute(k_gemm1_fp16, cudaFuncAttributeMaxDynamicSharedMemorySize, 2 * STAGE2B);
        cudaFuncSetAttribute(k_gemm2_fp16, cudaFuncAttributeMaxDynamicSharedMemorySize, 2 * STAGE2B);
        cudaFuncSetAttribute(k_proj_fp16, cudaFuncAttributeMaxDynamicSharedMemorySize, 2 * STAGE2B);
        attr_done = true;
    }

    // weight prep
    k_cvt16<<<(Vn * Dn / 4 + 255) / 256, 256>>>(embed, pBp, Vn * Dn / 4);
    k_tsplit3<<<dim3(Fn / 32, Dn / 32, En), dim3(32, 8)>>>(w1, pw1h, pw1l, pw1p, Dn, Fn);
    k_tsplit3<<<dim3(Dn / 32, Fn / 32, En), dim3(32, 8)>>>(w2, pw2h, pw2l, pw2p, Fn, Dn);

    k_embed<<<(Tn * Dn / 4) / 256, 256>>>(ids, embed);

    float* hin = hA;
    float* hout = hB;
    for (int hop = 0; hop < 2; hop++) {
        k_router<<<Tn, 256>>>(hin, router + (size_t)hop * Dn * En);
        k_scan<<<1, 256>>>();
        k_split3<<<(Tn * Dn / 4 + 255) / 256, 256>>>(hin, pAh, pAl, pAp, Tn * Dn / 4);
        k_scale<<<Tn, 256>>>(hin, hout);
        if (hop == 0) {
            k_gemm1_hmma<<<dim3(Fn / 128, (CAPn + 127) / 128, En), 256, 2 * STAGEB>>>(pAh, pAl);
            k_gemm2_hmma<<<dim3(Dn / 128, (CAPn + 127) / 128, En), 256, 2 * STAGEB>>>(hout);
        } else {
            k_gemm1_fp16<<<dim3(Fn / 128, (CAPn + 127) / 128, En), 256, 2 * STAGE2B>>>(pAp);
            k_gemm2_fp16<<<dim3(Dn / 128, (CAPn + 127) / 128, En), 256, 2 * STAGE2B>>>(hout);
        }
        float* tmp = hin; hin = hout; hout = tmp;
    }
    k_rms<<<Tn, 256>>>(hin, lnw, hout);
    k_split3<<<(Tn * Dn / 4 + 255) / 256, 256>>>(hout, pAh, pAl, pAp, Tn * Dn / 4);

    k_proj_fp16<<<dim3(Tn / 128, Vn / 128), 256, 2 * STAGE2B>>>(pAp, pBp, out);
}

// round 7
// speedup vs baseline: 4.3624x; 1.0530x over previous
#include <cuda_runtime.h>
#include <cuda_bf16.h>
#include <cuda_fp16.h>
#include <math.h>
#include <stdint.h>

#define Tn 2048
#define Dn 1024
#define En 8
#define Fn 2048
#define Vn 32000
#define CAPn 640

// ---------------- device scratch (no allocations allowed) ----------------
__device__ float g_hA[Tn * Dn];
__device__ float g_hB[Tn * Dn];
__device__ int   g_top2[Tn * 2];
__device__ float g_topw[Tn * 2];
__device__ float g_wkept[Tn * 2];
__device__ int   g_elist[En * CAPn];
__device__ float g_ew[En * CAPn];
__device__ int   g_ecnt[En];
__device__ __half g_Bp[(size_t)Vn * Dn];                 // embed fp16 (proj B)
__device__ __nv_bfloat16 g_Ah[Tn * Dn];                  // h split hi (router-safe path)
__device__ __nv_bfloat16 g_Al[Tn * Dn];                  // h split lo
__device__ __half g_Ap[Tn * Dn];                         // h fp16 (terminal path)
__device__ __nv_bfloat16 g_w1h[(size_t)En * Fn * Dn];    // w1^T hi [E][F][D]
__device__ __nv_bfloat16 g_w1l[(size_t)En * Fn * Dn];
__device__ __half        g_w1p[(size_t)En * Fn * Dn];    // w1^T fp16
__device__ __nv_bfloat16 g_w2h[(size_t)En * Dn * Fn];    // w2^T hi [E][D][F]
__device__ __nv_bfloat16 g_w2l[(size_t)En * Dn * Fn];
__device__ __half        g_w2p[(size_t)En * Dn * Fn];    // w2^T fp16
__device__ __nv_bfloat16 g_hidh[(size_t)En * CAPn * Fn]; // hop-1 hid split hi
__device__ __nv_bfloat16 g_hidl[(size_t)En * CAPn * Fn];
__device__ __half        g_hidp[(size_t)En * CAPn * Fn]; // hop-2 hid fp16

__device__ __forceinline__ float gelu_t(float x) {
    float u = 0.7978845608028654f * (x + 0.044715f * x * x * x);
    return 0.5f * x * (1.0f + tanhf(u));
}

// ---------------- hmma helpers ----------------
__device__ __forceinline__ uint32_t s2u(const void* p) {
    uint32_t a;
    asm("{ .reg .u64 t; cvta.to.shared.u64 t, %1; cvt.u32.u64 %0, t; }" : "=r"(a) : "l"(p));
    return a;
}
__device__ __forceinline__ void ldsm4(uint32_t* r, uint32_t a) {
    asm volatile("ldmatrix.sync.aligned.m8n8.x4.shared.b16 {%0,%1,%2,%3}, [%4];"
                 : "=r"(r[0]), "=r"(r[1]), "=r"(r[2]), "=r"(r[3]) : "r"(a));
}
__device__ __forceinline__ void mma16816(float* c, const uint32_t* a, uint32_t b0, uint32_t b1) {
    asm volatile("mma.sync.aligned.m16n8k16.row.col.f32.bf16.bf16.f32 "
                 "{%0,%1,%2,%3}, {%4,%5,%6,%7}, {%8,%9}, {%0,%1,%2,%3};"
                 : "+f"(c[0]), "+f"(c[1]), "+f"(c[2]), "+f"(c[3])
                 : "r"(a[0]), "r"(a[1]), "r"(a[2]), "r"(a[3]), "r"(b0), "r"(b1));
}
__device__ __forceinline__ void mma16816h(float* c, const uint32_t* a, uint32_t b0, uint32_t b1) {
    asm volatile("mma.sync.aligned.m16n8k16.row.col.f32.f16.f16.f32 "
                 "{%0,%1,%2,%3}, {%4,%5,%6,%7}, {%8,%9}, {%0,%1,%2,%3};"
                 : "+f"(c[0]), "+f"(c[1]), "+f"(c[2]), "+f"(c[3])
                 : "r"(a[0]), "r"(a[1]), "r"(a[2]), "r"(a[3]), "r"(b0), "r"(b1));
}
__device__ __forceinline__ void cpa16(uint32_t dst, const void* src) {
    asm volatile("cp.async.cg.shared.global [%0], [%1], 16;" :: "r"(dst), "l"(src) : "memory");
}
__device__ __forceinline__ void bsplit(float x, unsigned short& h, unsigned short& l) {
    __nv_bfloat16 hb = __float2bfloat16_rn(x);
    __nv_bfloat16 lb = __float2bfloat16_rn(x - __bfloat162float(hb));
    h = *(unsigned short*)&hb;
    l = *(unsigned short*)&lb;
}

// ---------------- embedding gather ----------------
__global__ void k_embed(const int* __restrict__ ids, const float* __restrict__ ew) {
    int i = blockIdx.x * blockDim.x + threadIdx.x;
    int t = i / (Dn / 4);
    int d4 = i % (Dn / 4);
    float4 v = ((const float4*)(ew + (size_t)ids[t] * Dn))[d4];
    ((float4*)(g_hA + (size_t)t * Dn))[d4] = v;
}

// ---------------- fp32 -> fp16 convert ----------------
__global__ void k_cvt16(const float* __restrict__ src, __half* __restrict__ dst, int n4) {
    int i = blockIdx.x * blockDim.x + threadIdx.x;
    if (i >= n4) return;
    float4 v = ((const float4*)src)[i];
    __half2 a = __floats2half2_rn(v.x, v.y);
    __half2 b = __floats2half2_rn(v.z, v.w);
    ((uint2*)dst)[i] = make_uint2(*(uint32_t*)&a, *(uint32_t*)&b);
}

// ---------------- fused: splits of hin (per-hop format) + hout = hin*(1-rho) ----------------
// mode 0: write bf16 hi/lo (hop-0 expert path). mode 1: write fp16 (hop-1 expert path).
__global__ void k_prep_h(const float* __restrict__ hin, float* __restrict__ hout,
                         __nv_bfloat16* __restrict__ hi, __nv_bfloat16* __restrict__ lo,
                         __half* __restrict__ fp, int mode) {
    int t = blockIdx.x;
    int i = (size_t)t * (Dn / 4) + threadIdx.x;
    float4 v = ((const float4*)hin)[i];
    if (mode == 0) {
        float x[4] = {v.x, v.y, v.z, v.w};
        unsigned short h[4], l[4];
        #pragma unroll
        for (int j = 0; j < 4; j++) bsplit(x[j], h[j], l[j]);
        ((uint2*)hi)[i] = make_uint2((uint32_t)h[0] | ((uint32_t)h[1] << 16),
                                     (uint32_t)h[2] | ((uint32_t)h[3] << 16));
        ((uint2*)lo)[i] = make_uint2((uint32_t)l[0] | ((uint32_t)l[1] << 16),
                                     (uint32_t)l[2] | ((uint32_t)l[3] << 16));
    } else {
        __half2 a = __floats2half2_rn(v.x, v.y);
        __half2 b = __floats2half2_rn(v.z, v.w);
        ((uint2*)fp)[i] = make_uint2(*(uint32_t*)&a, *(uint32_t*)&b);
    }
    float s = 1.0f - (g_wkept[2 * t] + g_wkept[2 * t + 1]);
    v.x *= s; v.y *= s; v.z *= s; v.w *= s;
    ((float4*)hout)[i] = v;
}

// ---------------- transpose+split: [E][R][C] fp32 -> [E][C][R] bf16 hi/lo + fp16 ----------------
__global__ void k_tsplit3(const float* __restrict__ src, __nv_bfloat16* __restrict__ hi,
                          __nv_bfloat16* __restrict__ lo, __half* __restrict__ fp,
                          int R, int C) {
    __shared__ float t[32][33];
    int e = blockIdx.z;
    const float* S = src + (size_t)e * R * C;
    __nv_bfloat16* H = hi + (size_t)e * R * C;
    __nv_bfloat16* L = lo + (size_t)e * R * C;
    __half* P = fp + (size_t)e * R * C;
    int c0 = blockIdx.x * 32, r0 = blockIdx.y * 32;
    int tx = threadIdx.x, ty = threadIdx.y;
    #pragma unroll
    for (int j = 0; j < 32; j += 8)
        t[ty + j][tx] = S[(size_t)(r0 + ty + j) * C + c0 + tx];
    __syncthreads();
    #pragma unroll
    for (int j = 0; j < 32; j += 8) {
        float v = t[tx][ty + j];
        unsigned short h, l;
        bsplit(v, h, l);
        size_t o = (size_t)(c0 + ty + j) * R + r0 + tx;
        H[o] = *(__nv_bfloat16*)&h;
        L[o] = *(__nv_bfloat16*)&l;
        P[o] = __float2half_rn(v);
    }
}

// ---------------- router ----------------
__global__ void k_router(const float* __restrict__ h, const float* __restrict__ rw) {
    int t = blockIdx.x;
    int lane = threadIdx.x & 31;
    int w = threadIdx.x >> 5;
    const float* hr = h + (size_t)t * Dn;
    float acc = 0.f;
    for (int d = lane; d < Dn; d += 32) acc += hr[d] * rw[d * En + w];
    #pragma unroll
    for (int o = 16; o; o >>= 1) acc += __shfl_xor_sync(0xFFFFFFFFu, acc, o);
    __shared__ float lg[En];
    if (lane == 0) lg[w] = acc;
    __syncthreads();
    if (threadIdx.x == 0) {
        float l[En];
        #pragma unroll
        for (int e = 0; e < En; e++) l[e] = lg[e];
        float m = l[0];
        #pragma unroll
        for (int e = 1; e < En; e++) m = fmaxf(m, l[e]);
        float p[En], s = 0.f;
        #pragma unroll
        for (int e = 0; e < En; e++) { p[e] = expf(l[e] - m); s += p[e]; }
        float inv = 1.0f / s;
        int i0 = 0;
        #pragma unroll
        for (int e = 1; e < En; e++) if (l[e] > l[i0]) i0 = e;
        int i1 = -1;
        #pragma unroll
        for (int e = 0; e < En; e++) {
            if (e == i0) continue;
            if (i1 < 0 || l[e] > l[i1]) i1 = e;
        }
        g_top2[2 * t] = i0;
        g_top2[2 * t + 1] = i1;
        g_topw[2 * t] = p[i0] * inv;
        g_topw[2 * t + 1] = p[i1] * inv;
        g_wkept[2 * t] = 0.f;
        g_wkept[2 * t + 1] = 0.f;
    }
}

// ---------------- capacity scan (smem-staged) ----------------
__global__ void k_scan() {
    __shared__ int s_top[Tn * 2];
    for (int i = threadIdx.x; i < Tn * 2; i += 256) s_top[i] = g_top2[i];
    __syncthreads();
    int lane = threadIdx.x & 31;
    int e = threadIdx.x >> 5;
    if (e >= En) return;
    int base = 0;
    for (int t0 = 0; t0 < Tn; t0 += 32) {
        int t = t0 + lane;
        int a = s_top[2 * t], b = s_top[2 * t + 1];
        int j = (a == e) ? 0 : ((b == e) ? 1 : -1);
        unsigned bal = __ballot_sync(0xFFFFFFFFu, j >= 0);
        int rank = base + __popc(bal & (0xFFFFFFFFu >> (31 - lane)));
        if (j >= 0 && rank <= CAPn) {
            int slot = rank - 1;
            g_elist[e * CAPn + slot] = t;
            float wv = g_topw[2 * t + j];
            g_ew[e * CAPn + slot] = wv;
            g_wkept[2 * t + j] = wv;
        }
        base += __popc(bal);
    }
    if (lane == 0) g_ecnt[e] = base < CAPn ? base : CAPn;
}

// ---------------- fused final rmsnorm -> fp16 (proj A operand) ----------------
__global__ void k_rms_fp16(const float* __restrict__ hin, const float* __restrict__ lnw,
                           __half* __restrict__ Ap) {
    int t = blockIdx.x;
    int lane = threadIdx.x & 31, wid = threadIdx.x >> 5;
    float4 v = ((const float4*)(hin + (size_t)t * Dn))[threadIdx.x];
    float s = v.x * v.x + v.y * v.y + v.z * v.z + v.w * v.w;
    #pragma unroll
    for (int o = 16; o; o >>= 1) s += __shfl_xor_sync(0xFFFFFFFFu, s, o);
    __shared__ float red[8];
    if (lane == 0) red[wid] = s;
    __syncthreads();
    float tot = 0.f;
    #pragma unroll
    for (int i = 0; i < 8; i++) tot += red[i];
    float sc = rsqrtf(tot * (1.0f / Dn) + 1e-6f);
    float4 w = ((const float4*)lnw)[threadIdx.x];
    __half2 a = __floats2half2_rn(v.x * sc * w.x, v.y * sc * w.y);
    __half2 b = __floats2half2_rn(v.z * sc * w.z, v.w * sc * w.w);
    ((uint2*)(Ap + (size_t)t * Dn))[threadIdx.x] = make_uint2(*(uint32_t*)&a, *(uint32_t*)&b);
}

// ================= HMMA tile framework =================
#define ROWB 80
#define ARRB (128 * ROWB)
#define STAGEB (4 * ARRB)            // bf16 3-term: 4 operand tiles
#define STAGE2B (2 * ARRB)           // fp16 single: 2 operand tiles

#define HMMA_PROLOG \
    extern __shared__ char smraw[]; \
    const uint32_t sbase = s2u(smraw); \
    const int tid = threadIdx.x; \
    const int lane = tid & 31; \
    const int wm = (tid >> 5) & 3; \
    const int wn = tid >> 7; \
    float acc[2][8][4]; \
    _Pragma("unroll") for (int i = 0; i < 2; i++) \
        _Pragma("unroll") for (int j = 0; j < 8; j++) \
            _Pragma("unroll") for (int q = 0; q < 4; q++) acc[i][j][q] = 0.f; \
    const int a_lr = lane & 15; \
    const int a_lc = ((lane >> 4) << 3); \
    const int b_nr = ((lane >> 4) << 3) + (lane & 7); \
    const int b_kc = (lane & 8);

#define HMMA_MAINLOOP(NCHKv) \
    load_stage(0, 0); \
    load_stage(1, 1); \
    for (int c = 0; c < (NCHKv); c++) { \
        const int st = c & 1; \
        if (c + 1 < (NCHKv)) asm volatile("cp.async.wait_group 1;" ::: "memory"); \
        else                 asm volatile("cp.async.wait_group 0;" ::: "memory"); \
        __syncthreads(); \
        const uint32_t sb = sbase + st * STAGEB; \
        _Pragma("unroll") \
        for (int k16 = 0; k16 < 32; k16 += 16) { \
            uint32_t ah[2][4], al[2][4]; \
            _Pragma("unroll") \
            for (int mi = 0; mi < 2; mi++) { \
                uint32_t aoff = (uint32_t)((wm * 32 + mi * 16 + a_lr) * ROWB + (k16 + a_lc) * 2); \
                ldsm4(ah[mi], sb + aoff); \
                ldsm4(al[mi], sb + ARRB + aoff); \
            } \
            _Pragma("unroll") \
            for (int ng = 0; ng < 4; ng++) { \
                uint32_t boff = (uint32_t)((wn * 64 + ng * 16 + b_nr) * ROWB + (k16 + b_kc) * 2); \
                uint32_t bh[4], bl[4]; \
                ldsm4(bh, sb + 2 * ARRB + boff); \
                ldsm4(bl, sb + 3 * ARRB + boff); \
                _Pragma("unroll") \
                for (int hv = 0; hv < 2; hv++) { \
                    const int nj = ng * 2 + hv; \
                    _Pragma("unroll") \
                    for (int mi = 0; mi < 2; mi++) { \
                        mma16816(acc[mi][nj], ah[mi], bh[2 * hv], bh[2 * hv + 1]); \
                        mma16816(acc[mi][nj], al[mi], bh[2 * hv], bh[2 * hv + 1]); \
                        mma16816(acc[mi][nj], ah[mi], bl[2 * hv], bl[2 * hv + 1]); \
                    } \
                } \
            } \
        } \
        __syncthreads(); \
        if (c + 2 < (NCHKv)) load_stage(c + 2, st); \
    }

#define HMMA16_MAINLOOP(NCHKv) \
    load_stage(0, 0); \
    load_stage(1, 1); \
    for (int c = 0; c < (NCHKv); c++) { \
        const int st = c & 1; \
        if (c + 1 < (NCHKv)) asm volatile("cp.async.wait_group 1;" ::: "memory"); \
        else                 asm volatile("cp.async.wait_group 0;" ::: "memory"); \
        __syncthreads(); \
        const uint32_t sb = sbase + st * STAGE2B; \
        _Pragma("unroll") \
        for (int k16 = 0; k16 < 32; k16 += 16) { \
            uint32_t af[2][4]; \
            _Pragma("unroll") \
            for (int mi = 0; mi < 2; mi++) { \
                uint32_t aoff = (uint32_t)((wm * 32 + mi * 16 + a_lr) * ROWB + (k16 + a_lc) * 2); \
                ldsm4(af[mi], sb + aoff); \
            } \
            _Pragma("unroll") \
            for (int ng = 0; ng < 4; ng++) { \
                uint32_t boff = (uint32_t)((wn * 64 + ng * 16 + b_nr) * ROWB + (k16 + b_kc) * 2); \
                uint32_t bf[4]; \
                ldsm4(bf, sb + ARRB + boff); \
                _Pragma("unroll") \
                for (int hv = 0; hv < 2; hv++) { \
                    const int nj = ng * 2 + hv; \
                    _Pragma("unroll") \
                    for (int mi = 0; mi < 2; mi++) \
                        mma16816h(acc[mi][nj], af[mi], bf[2 * hv], bf[2 * hv + 1]); \
                } \
            } \
        } \
        __syncthreads(); \
        if (c + 2 < (NCHKv)) load_stage(c + 2, st); \
    }

// ---------------- hop-1 GEMM1 (bf16 3-term): hid = gelu(gather(h) @ w1) ----------------
__global__ __launch_bounds__(256, 2)
void k_gemm1_hmma(const __nv_bfloat16* __restrict__ Ah, const __nv_bfloat16* __restrict__ Al) {
    const int e = blockIdx.z;
    const int cnt = g_ecnt[e];
    const int m0 = blockIdx.y * 128;
    if (m0 >= cnt) return;
    HMMA_PROLOG
    const int n0 = blockIdx.x * 128;
    const __nv_bfloat16* Wh = g_w1h + (size_t)e * Fn * Dn;
    const __nv_bfloat16* Wl = g_w1l + (size_t)e * Fn * Dn;
    size_t gaA[2], gaB[2];
    uint32_t soff[2];
    #pragma unroll
    for (int hf = 0; hf < 2; hf++) {
        int id = tid + hf * 256;
        int row = id >> 2, seg = id & 3;
        int mrow = m0 + row;
        if (mrow >= cnt) mrow = cnt - 1;
        int tok = g_elist[e * CAPn + mrow];
        gaA[hf] = (size_t)tok * Dn + seg * 8;
        gaB[hf] = (size_t)(n0 + row) * Dn + seg * 8;
        soff[hf] = (uint32_t)(row * ROWB + seg * 16);
    }
    auto load_stage = [&](int c, int st) {
        const int kb = c * 32;
        const uint32_t sb = sbase + st * STAGEB;
        #pragma unroll
        for (int hf = 0; hf < 2; hf++) {
            cpa16(sb + soff[hf], Ah + gaA[hf] + kb);
            cpa16(sb + ARRB + soff[hf], Al + gaA[hf] + kb);
            cpa16(sb + 2 * ARRB + soff[hf], Wh + gaB[hf] + kb);
            cpa16(sb + 3 * ARRB + soff[hf], Wl + gaB[hf] + kb);
        }
        asm volatile("cp.async.commit_group;" ::: "memory");
    };
    HMMA_MAINLOOP(Dn / 32)
    __nv_bfloat16* Hh = g_hidh + (size_t)e * CAPn * Fn;
    __nv_bfloat16* Hl = g_hidl + (size_t)e * CAPn * Fn;
    const int g = lane >> 2, t2 = (lane & 3) << 1;
    #pragma unroll
    for (int mi = 0; mi < 2; mi++) {
        int r = wm * 32 + mi * 16 + g;
        #pragma unroll
        for (int nj = 0; nj < 8; nj++) {
            int col = n0 + wn * 64 + nj * 8 + t2;
            int s0 = m0 + r, s1 = m0 + r + 8;
            if (s0 < cnt) {
                float x0 = gelu_t(acc[mi][nj][0]), x1 = gelu_t(acc[mi][nj][1]);
                unsigned short h0, l0, h1, l1;
                bsplit(x0, h0, l0);
                bsplit(x1, h1, l1);
                *(uint32_t*)&Hh[(size_t)s0 * Fn + col] = (uint32_t)h0 | ((uint32_t)h1 << 16);
                *(uint32_t*)&Hl[(size_t)s0 * Fn + col] = (uint32_t)l0 | ((uint32_t)l1 << 16);
            }
            if (s1 < cnt) {
                float x2 = gelu_t(acc[mi][nj][2]), x3 = gelu_t(acc[mi][nj][3]);
                unsigned short h2, l2, h3, l3;
                bsplit(x2, h2, l2);
                bsplit(x3, h3, l3);
                *(uint32_t*)&Hh[(size_t)s1 * Fn + col] = (uint32_t)h2 | ((uint32_t)h3 << 16);
                *(uint32_t*)&Hl[(size_t)s1 * Fn + col] = (uint32_t)l2 | ((uint32_t)l3 << 16);
            }
        }
    }
}

// ---------------- hop-1 GEMM2 (bf16 3-term): scatter ----------------
__global__ __launch_bounds__(256, 2)
void k_gemm2_hmma(float* __restrict__ hout) {
    const int e = blockIdx.z;
    const int cnt = g_ecnt[e];
    const int m0 = blockIdx.y * 128;
    if (m0 >= cnt) return;
    HMMA_PROLOG
    const int n0 = blockIdx.x * 128;
    const __nv_bfloat16* Ahp = g_hidh + (size_t)e * CAPn * Fn;
    const __nv_bfloat16* Alp = g_hidl + (size_t)e * CAPn * Fn;
    const __nv_bfloat16* Wh = g_w2h + (size_t)e * Dn * Fn;
    const __nv_bfloat16* Wl = g_w2l + (size_t)e * Dn * Fn;
    size_t gaA[2], gaB[2];
    uint32_t soff[2];
    #pragma unroll
    for (int hf = 0; hf < 2; hf++) {
        int id = tid + hf * 256;
        int row = id >> 2, seg = id & 3;
        gaA[hf] = (size_t)(m0 + row) * Fn + seg * 8;
        gaB[hf] = (size_t)(n0 + row) * Fn + seg * 8;
        soff[hf] = (uint32_t)(row * ROWB + seg * 16);
    }
    auto load_stage = [&](int c, int st) {
        const int kb = c * 32;
        const uint32_t sb = sbase + st * STAGEB;
        #pragma unroll
        for (int hf = 0; hf < 2; hf++) {
            cpa16(sb + soff[hf], Ahp + gaA[hf] + kb);
            cpa16(sb + ARRB + soff[hf], Alp + gaA[hf] + kb);
            cpa16(sb + 2 * ARRB + soff[hf], Wh + gaB[hf] + kb);
            cpa16(sb + 3 * ARRB + soff[hf], Wl + gaB[hf] + kb);
        }
        asm volatile("cp.async.commit_group;" ::: "memory");
    };
    HMMA_MAINLOOP(Fn / 32)
    const int g = lane >> 2, t2 = (lane & 3) << 1;
    #pragma unroll
    for (int mi = 0; mi < 2; mi++) {
        int r = wm * 32 + mi * 16 + g;
        int s0 = m0 + r, s1 = m0 + r + 8;
        int tok0 = 0, tok1 = 0;
        float w0 = 0.f, w1v = 0.f;
        if (s0 < cnt) { tok0 = g_elist[e * CAPn + s0]; w0 = g_ew[e * CAPn + s0]; }
        if (s1 < cnt) { tok1 = g_elist[e * CAPn + s1]; w1v = g_ew[e * CAPn + s1]; }
        #pragma unroll
        for (int nj = 0; nj < 8; nj++) {
            int col = n0 + wn * 64 + nj * 8 + t2;
            if (s0 < cnt) {
                atomicAdd(&hout[(size_t)tok0 * Dn + col], w0 * acc[mi][nj][0]);
                atomicAdd(&hout[(size_t)tok0 * Dn + col + 1], w0 * acc[mi][nj][1]);
            }
            if (s1 < cnt) {
                atomicAdd(&hout[(size_t)tok1 * Dn + col], w1v * acc[mi][nj][2]);
                atomicAdd(&hout[(size_t)tok1 * Dn + col + 1], w1v * acc[mi][nj][3]);
            }
        }
    }
}

// ---------------- hop-2 GEMM1 (fp16 single) ----------------
__global__ __launch_bounds__(256, 2)
void k_gemm1_fp16(const __half* __restrict__ Ap) {
    const int e = blockIdx.z;
    const int cnt = g_ecnt[e];
    const int m0 = blockIdx.y * 128;
    if (m0 >= cnt) return;
    HMMA_PROLOG
    const int n0 = blockIdx.x * 128;
    const __half* Wp = g_w1p + (size_t)e * Fn * Dn;
    size_t gaA[2], gaB[2];
    uint32_t soff[2];
    #pragma unroll
    for (int hf = 0; hf < 2; hf++) {
        int id = tid + hf * 256;
        int row = id >> 2, seg = id & 3;
        int mrow = m0 + row;
        if (mrow >= cnt) mrow = cnt - 1;
        int tok = g_elist[e * CAPn + mrow];
        gaA[hf] = (size_t)tok * Dn + seg * 8;
        gaB[hf] = (size_t)(n0 + row) * Dn + seg * 8;
        soff[hf] = (uint32_t)(row * ROWB + seg * 16);
    }
    auto load_stage = [&](int c, int st) {
        const int kb = c * 32;
        const uint32_t sb = sbase + st * STAGE2B;
        #pragma unroll
        for (int hf = 0; hf < 2; hf++) {
            cpa16(sb + soff[hf], Ap + gaA[hf] + kb);
            cpa16(sb + ARRB + soff[hf], Wp + gaB[hf] + kb);
        }
        asm volatile("cp.async.commit_group;" ::: "memory");
    };
    HMMA16_MAINLOOP(Dn / 32)
    __half* Hp = g_hidp + (size_t)e * CAPn * Fn;
    const int g = lane >> 2, t2 = (lane & 3) << 1;
    #pragma unroll
    for (int mi = 0; mi < 2; mi++) {
        int r = wm * 32 + mi * 16 + g;
        #pragma unroll
        for (int nj = 0; nj < 8; nj++) {
            int col = n0 + wn * 64 + nj * 8 + t2;
            int s0 = m0 + r, s1 = m0 + r + 8;
            if (s0 < cnt) {
                __half2 p = __floats2half2_rn(gelu_t(acc[mi][nj][0]), gelu_t(acc[mi][nj][1]));
                *(uint32_t*)&Hp[(size_t)s0 * Fn + col] = *(uint32_t*)&p;
            }
            if (s1 < cnt) {
                __half2 p = __floats2half2_rn(gelu_t(acc[mi][nj][2]), gelu_t(acc[mi][nj][3]));
                *(uint32_t*)&Hp[(size_t)s1 * Fn + col] = *(uint32_t*)&p;
            }
        }
    }
}

// ---------------- hop-2 GEMM2 (fp16 single): scatter ----------------
__global__ __launch_bounds__(256, 2)
void k_gemm2_fp16(float* __restrict__ hout) {
    const int e = blockIdx.z;
    const int cnt = g_ecnt[e];
    const int m0 = blockIdx.y * 128;
    if (m0 >= cnt) return;
    HMMA_PROLOG
    const int n0 = blockIdx.x * 128;
    const __half* Apx = g_hidp + (size_t)e * CAPn * Fn;
    const __half* Wp = g_w2p + (size_t)e * Dn * Fn;
    size_t gaA[2], gaB[2];
    uint32_t soff[2];
    #pragma unroll
    for (int hf = 0; hf < 2; hf++) {
        int id = tid + hf * 256;
        int row = id >> 2, seg = id & 3;
        gaA[hf] = (size_t)(m0 + row) * Fn + seg * 8;
        gaB[hf] = (size_t)(n0 + row) * Fn + seg * 8;
        soff[hf] = (uint32_t)(row * ROWB + seg * 16);
    }
    auto load_stage = [&](int c, int st) {
        const int kb = c * 32;
        const uint32_t sb = sbase + st * STAGE2B;
        #pragma unroll
        for (int hf = 0; hf < 2; hf++) {
            cpa16(sb + soff[hf], Apx + gaA[hf] + kb);
            cpa16(sb + ARRB + soff[hf], Wp + gaB[hf] + kb);
        }
        asm volatile("cp.async.commit_group;" ::: "memory");
    };
    HMMA16_MAINLOOP(Fn / 32)
    const int g = lane >> 2, t2 = (lane & 3) << 1;
    #pragma unroll
    for (int mi = 0; mi < 2; mi++) {
        int r = wm * 32 + mi * 16 + g;
        int s0 = m0 + r, s1 = m0 + r + 8;
        int tok0 = 0, tok1 = 0;
        float w0 = 0.f, w1v = 0.f;
        if (s0 < cnt) { tok0 = g_elist[e * CAPn + s0]; w0 = g_ew[e * CAPn + s0]; }
        if (s1 < cnt) { tok1 = g_elist[e * CAPn + s1]; w1v = g_ew[e * CAPn + s1]; }
        #pragma unroll
        for (int nj = 0; nj < 8; nj++) {
            int col = n0 + wn * 64 + nj * 8 + t2;
            if (s0 < cnt) {
                atomicAdd(&hout[(size_t)tok0 * Dn + col], w0 * acc[mi][nj][0]);
                atomicAdd(&hout[(size_t)tok0 * Dn + col + 1], w0 * acc[mi][nj][1]);
            }
            if (s1 < cnt) {
                atomicAdd(&hout[(size_t)tok1 * Dn + col], w1v * acc[mi][nj][2]);
                atomicAdd(&hout[(size_t)tok1 * Dn + col + 1], w1v * acc[mi][nj][3]);
            }
        }
    }
}

// ---------------- tied projection (fp16 single): C = Ap . Bp^T ----------------
__global__ __launch_bounds__(256, 2)
void k_proj_fp16(const __half* __restrict__ Ap, const __half* __restrict__ Bp,
                 float* __restrict__ C) {
    HMMA_PROLOG
    const int m0 = blockIdx.x * 128;
    const int n0 = blockIdx.y * 128;
    size_t gaA[2], gaB[2];
    uint32_t soff[2];
    #pragma unroll
    for (int hf = 0; hf < 2; hf++) {
        int id = tid + hf * 256;
        int row = id >> 2, seg = id & 3;
        gaA[hf] = (size_t)(m0 + row) * Dn + seg * 8;
        gaB[hf] = (size_t)(n0 + row) * Dn + seg * 8;
        soff[hf] = (uint32_t)(row * ROWB + seg * 16);
    }
    auto load_stage = [&](int c, int st) {
        const int kb = c * 32;
        const uint32_t sb = sbase + st * STAGE2B;
        #pragma unroll
        for (int hf = 0; hf < 2; hf++) {
            cpa16(sb + soff[hf], Ap + gaA[hf] + kb);
            cpa16(sb + ARRB + soff[hf], Bp + gaB[hf] + kb);
        }
        asm volatile("cp.async.commit_group;" ::: "memory");
    };
    HMMA16_MAINLOOP(Dn / 32)
    const int g = lane >> 2, t2 = (lane & 3) << 1;
    #pragma unroll
    for (int mi = 0; mi < 2; mi++) {
        #pragma unroll
        for (int nj = 0; nj < 8; nj++) {
            int r = m0 + wm * 32 + mi * 16 + g;
            int col = n0 + wn * 64 + nj * 8 + t2;
            *(float2*)&C[(size_t)r * Vn + col] = make_float2(acc[mi][nj][0], acc[mi][nj][1]);
            *(float2*)&C[(size_t)(r + 8) * Vn + col] = make_float2(acc[mi][nj][2], acc[mi][nj][3]);
        }
    }
}

// ---------------- launch ----------------
extern "C" void kernel_launch(void* const* d_in, const int* in_sizes, int n_in,
                              void* d_out, int out_size) {
    (void)in_sizes; (void)n_in; (void)out_size;
    const int*   ids    = (const int*)d_in[0];
    const float* embed  = (const float*)d_in[1];
    const float* router = (const float*)d_in[2];
    const float* w1     = (const float*)d_in[3];
    const float* w2     = (const float*)d_in[4];
    const float* lnw    = (const float*)d_in[5];
    float* out = (float*)d_out;

    float *hA, *hB;
    __half *pBp, *pAp, *pw1p, *pw2p;
    __nv_bfloat16 *pAh, *pAl, *pw1h, *pw1l, *pw2h, *pw2l;
    cudaGetSymbolAddress((void**)&hA, g_hA);
    cudaGetSymbolAddress((void**)&hB, g_hB);
    cudaGetSymbolAddress((void**)&pBp, g_Bp);
    cudaGetSymbolAddress((void**)&pAh, g_Ah);
    cudaGetSymbolAddress((void**)&pAl, g_Al);
    cudaGetSymbolAddress((void**)&pAp, g_Ap);
    cudaGetSymbolAddress((void**)&pw1h, g_w1h);
    cudaGetSymbolAddress((void**)&pw1l, g_w1l);
    cudaGetSymbolAddress((void**)&pw1p, g_w1p);
    cudaGetSymbolAddress((void**)&pw2h, g_w2h);
    cudaGetSymbolAddress((void**)&pw2l, g_w2l);
    cudaGetSymbolAddress((void**)&pw2p, g_w2p);

    static bool attr_done = false;
    if (!attr_done) {
        cudaFuncSetAttribute(k_gemm1_hmma, cudaFuncAttributeMaxDynamicSharedMemorySize, 2 * STAGEB);
        cudaFuncSetAttribute(k_gemm2_hmma, cudaFuncAttributeMaxDynamicSharedMemorySize, 2 * STAGEB);
        cudaFuncSetAttribute(k_gemm1_fp16, cudaFuncAttributeMaxDynamicSharedMemorySize, 2 * STAGE2B);
        cudaFuncSetAttribute(k_gemm2_fp16, cudaFuncAttributeMaxDynamicSharedMemorySize, 2 * STAGE2B);
        cudaFuncSetAttribute(k_proj_fp16, cudaFuncAttributeMaxDynamicSharedMemorySize, 2 * STAGE2B);
        attr_done = true;
    }

    // weight prep (runs every call; deterministic)
    k_cvt16<<<(Vn * Dn / 4 + 255) / 256, 256>>>(embed, pBp, Vn * Dn / 4);
    k_tsplit3<<<dim3(Fn / 32, Dn / 32, En), dim3(32, 8)>>>(w1, pw1h, pw1l, pw1p, Dn, Fn);
    k_tsplit3<<<dim3(Dn / 32, Fn / 32, En), dim3(32, 8)>>>(w2, pw2h, pw2l, pw2p, Fn, Dn);

    k_embed<<<(Tn * Dn / 4) / 256, 256>>>(ids, embed);

    float* hin = hA;
    float* hout = hB;
    for (int hop = 0; hop < 2; hop++) {
        k_router<<<Tn, 256>>>(hin, router + (size_t)hop * Dn * En);
        k_scan<<<1, 256>>>();
        k_prep_h<<<Tn, 256>>>(hin, hout, pAh, pAl, pAp, hop);
        if (hop == 0) {
            k_gemm1_hmma<<<dim3(Fn / 128, (CAPn + 127) / 128, En), 256, 2 * STAGEB>>>(pAh, pAl);
            k_gemm2_hmma<<<dim3(Dn / 128, (CAPn + 127) / 128, En), 256, 2 * STAGEB>>>(hout);
        } else {
            k_gemm1_fp16<<<dim3(Fn / 128, (CAPn + 127) / 128, En), 256, 2 * STAGE2B>>>(pAp);
            k_gemm2_fp16<<<dim3(Dn / 128, (CAPn + 127) / 128, En), 256, 2 * STAGE2B>>>(hout);
        }
        float* tmp = hin; hin = hout; hout = tmp;
    }
    k_rms_fp16<<<Tn, 256>>>(hin, lnw, pAp);

    k_proj_fp16<<<dim3(Tn / 128, Vn / 128), 256, 2 * STAGE2B>>>(pAp, pBp, out);
}

// round 9
// speedup vs baseline: 4.3703x; 1.0018x over previous
#include <cuda_runtime.h>
#include <cuda_bf16.h>
#include <cuda_fp16.h>
#include <math.h>
#include <stdint.h>

#define Tn 2048
#define Dn 1024
#define En 8
#define Fn 2048
#define Vn 32000
#define CAPn 640

// ---------------- device scratch (no allocations allowed) ----------------
__device__ float g_hA[Tn * Dn];
__device__ float g_hB[Tn * Dn];
__device__ int   g_top2[Tn * 2];
__device__ float g_topw[Tn * 2];
__device__ float g_wkept[Tn * 2];
__device__ int   g_elist[En * CAPn];
__device__ float g_ew[En * CAPn];
__device__ int   g_ecnt[En];
__device__ __half g_Bp[(size_t)Vn * Dn];                 // embed fp16 (proj B)
__device__ __nv_bfloat16 g_Ah[Tn * Dn];                  // h split hi (router-safe path)
__device__ __nv_bfloat16 g_Al[Tn * Dn];                  // h split lo
__device__ __half g_Ap[Tn * Dn];                         // h fp16 (terminal path)
__device__ __nv_bfloat16 g_w1h[(size_t)En * Fn * Dn];    // w1^T hi [E][F][D]
__device__ __nv_bfloat16 g_w1l[(size_t)En * Fn * Dn];
__device__ __half        g_w1p[(size_t)En * Fn * Dn];    // w1^T fp16
__device__ __nv_bfloat16 g_w2h[(size_t)En * Dn * Fn];    // w2^T hi [E][D][F]
__device__ __nv_bfloat16 g_w2l[(size_t)En * Dn * Fn];
__device__ __half        g_w2p[(size_t)En * Dn * Fn];    // w2^T fp16
__device__ __nv_bfloat16 g_hidh[(size_t)En * CAPn * Fn]; // hop-1 hid split hi
__device__ __nv_bfloat16 g_hidl[(size_t)En * CAPn * Fn];
__device__ __half        g_hidp[(size_t)En * CAPn * Fn]; // hop-2 hid fp16

__device__ __forceinline__ float gelu_t(float x) {
    float u = 0.7978845608028654f * (x + 0.044715f * x * x * x);
    return 0.5f * x * (1.0f + tanhf(u));
}

// ---------------- hmma helpers ----------------
__device__ __forceinline__ uint32_t s2u(const void* p) {
    uint32_t a;
    asm("{ .reg .u64 t; cvta.to.shared.u64 t, %1; cvt.u32.u64 %0, t; }" : "=r"(a) : "l"(p));
    return a;
}
__device__ __forceinline__ void ldsm4(uint32_t* r, uint32_t a) {
    asm volatile("ldmatrix.sync.aligned.m8n8.x4.shared.b16 {%0,%1,%2,%3}, [%4];"
                 : "=r"(r[0]), "=r"(r[1]), "=r"(r[2]), "=r"(r[3]) : "r"(a));
}
__device__ __forceinline__ void mma16816(float* c, const uint32_t* a, uint32_t b0, uint32_t b1) {
    asm volatile("mma.sync.aligned.m16n8k16.row.col.f32.bf16.bf16.f32 "
                 "{%0,%1,%2,%3}, {%4,%5,%6,%7}, {%8,%9}, {%0,%1,%2,%3};"
                 : "+f"(c[0]), "+f"(c[1]), "+f"(c[2]), "+f"(c[3])
                 : "r"(a[0]), "r"(a[1]), "r"(a[2]), "r"(a[3]), "r"(b0), "r"(b1));
}
__device__ __forceinline__ void mma16816h(float* c, const uint32_t* a, uint32_t b0, uint32_t b1) {
    asm volatile("mma.sync.aligned.m16n8k16.row.col.f32.f16.f16.f32 "
                 "{%0,%1,%2,%3}, {%4,%5,%6,%7}, {%8,%9}, {%0,%1,%2,%3};"
                 : "+f"(c[0]), "+f"(c[1]), "+f"(c[2]), "+f"(c[3])
                 : "r"(a[0]), "r"(a[1]), "r"(a[2]), "r"(a[3]), "r"(b0), "r"(b1));
}
__device__ __forceinline__ void cpa16(uint32_t dst, const void* src) {
    asm volatile("cp.async.cg.shared.global [%0], [%1], 16;" :: "r"(dst), "l"(src) : "memory");
}
__device__ __forceinline__ void bsplit(float x, unsigned short& h, unsigned short& l) {
    __nv_bfloat16 hb = __float2bfloat16_rn(x);
    __nv_bfloat16 lb = __float2bfloat16_rn(x - __bfloat162float(hb));
    h = *(unsigned short*)&hb;
    l = *(unsigned short*)&lb;
}

// ---------------- embedding gather ----------------
__global__ void k_embed(const int* __restrict__ ids, const float* __restrict__ ew) {
    int i = blockIdx.x * blockDim.x + threadIdx.x;
    int t = i / (Dn / 4);
    int d4 = i % (Dn / 4);
    float4 v = ((const float4*)(ew + (size_t)ids[t] * Dn))[d4];
    ((float4*)(g_hA + (size_t)t * Dn))[d4] = v;
}

// ---------------- fp32 -> fp16 convert ----------------
__global__ void k_cvt16(const float* __restrict__ src, __half* __restrict__ dst, int n4) {
    int i = blockIdx.x * blockDim.x + threadIdx.x;
    if (i >= n4) return;
    float4 v = ((const float4*)src)[i];
    __half2 a = __floats2half2_rn(v.x, v.y);
    __half2 b = __floats2half2_rn(v.z, v.w);
    ((uint2*)dst)[i] = make_uint2(*(uint32_t*)&a, *(uint32_t*)&b);
}

// ---------------- fused: splits of hin (per-hop format) + hout = hin*(1-rho) ----------------
__global__ void k_prep_h(const float* __restrict__ hin, float* __restrict__ hout,
                         __nv_bfloat16* __restrict__ hi, __nv_bfloat16* __restrict__ lo,
                         __half* __restrict__ fp, int mode) {
    int t = blockIdx.x;
    int i = (size_t)t * (Dn / 4) + threadIdx.x;
    float4 v = ((const float4*)hin)[i];
    if (mode == 0) {
        float x[4] = {v.x, v.y, v.z, v.w};
        unsigned short h[4], l[4];
        #pragma unroll
        for (int j = 0; j < 4; j++) bsplit(x[j], h[j], l[j]);
        ((uint2*)hi)[i] = make_uint2((uint32_t)h[0] | ((uint32_t)h[1] << 16),
                                     (uint32_t)h[2] | ((uint32_t)h[3] << 16));
        ((uint2*)lo)[i] = make_uint2((uint32_t)l[0] | ((uint32_t)l[1] << 16),
                                     (uint32_t)l[2] | ((uint32_t)l[3] << 16));
    } else {
        __half2 a = __floats2half2_rn(v.x, v.y);
        __half2 b = __floats2half2_rn(v.z, v.w);
        ((uint2*)fp)[i] = make_uint2(*(uint32_t*)&a, *(uint32_t*)&b);
    }
    float s = 1.0f - (g_wkept[2 * t] + g_wkept[2 * t + 1]);
    v.x *= s; v.y *= s; v.z *= s; v.w *= s;
    ((float4*)hout)[i] = v;
}

// ---------------- transpose+split (bf16 pair): [E][R][C] fp32 -> [E][C][R] bf16 hi/lo ----------------
// Tile 64 R x 32 C; 256 threads. Store phase: 16B vector stores, 4 contiguous
// 128B row-runs per warp (vs 2B/thread scattered before).
__global__ void k_tsplit_bf(const float* __restrict__ src, __nv_bfloat16* __restrict__ hi,
                            __nv_bfloat16* __restrict__ lo, int R, int C) {
    __shared__ float t[64][33];
    int e = blockIdx.z;
    const float* S = src + (size_t)e * R * C;
    __nv_bfloat16* H = hi + (size_t)e * R * C;
    __nv_bfloat16* L = lo + (size_t)e * R * C;
    int c0 = blockIdx.x * 32, r0 = blockIdx.y * 64;
    int tx = threadIdx.x & 31, ty = threadIdx.x >> 5;       // ty 0..7
    #pragma unroll
    for (int j = 0; j < 8; j++)
        t[ty + j * 8][tx] = S[(size_t)(r0 + ty + j * 8) * C + c0 + tx];
    __syncthreads();
    int c = threadIdx.x >> 3, ri = threadIdx.x & 7;         // c 0..31, ri 0..7
    unsigned short hb[8], lb[8];
    #pragma unroll
    for (int i = 0; i < 8; i++) bsplit(t[ri * 8 + i][c], hb[i], lb[i]);
    size_t o = (size_t)(c0 + c) * R + r0 + ri * 8;
    *(uint4*)&H[o] = make_uint4((uint32_t)hb[0] | ((uint32_t)hb[1] << 16),
                                (uint32_t)hb[2] | ((uint32_t)hb[3] << 16),
                                (uint32_t)hb[4] | ((uint32_t)hb[5] << 16),
                                (uint32_t)hb[6] | ((uint32_t)hb[7] << 16));
    *(uint4*)&L[o] = make_uint4((uint32_t)lb[0] | ((uint32_t)lb[1] << 16),
                                (uint32_t)lb[2] | ((uint32_t)lb[3] << 16),
                                (uint32_t)lb[4] | ((uint32_t)lb[5] << 16),
                                (uint32_t)lb[6] | ((uint32_t)lb[7] << 16));
}

// ---------------- transpose+convert (fp16): [E][R][C] fp32 -> [E][C][R] fp16 ----------------
__global__ void k_tsplit_fp(const float* __restrict__ src, __half* __restrict__ fp,
                            int R, int C) {
    __shared__ float t[64][33];
    int e = blockIdx.z;
    const float* S = src + (size_t)e * R * C;
    __half* P = fp + (size_t)e * R * C;
    int c0 = blockIdx.x * 32, r0 = blockIdx.y * 64;
    int tx = threadIdx.x & 31, ty = threadIdx.x >> 5;
    #pragma unroll
    for (int j = 0; j < 8; j++)
        t[ty + j * 8][tx] = S[(size_t)(r0 + ty + j * 8) * C + c0 + tx];
    __syncthreads();
    int c = threadIdx.x >> 3, ri = threadIdx.x & 7;
    uint32_t pk[4];
    #pragma unroll
    for (int i = 0; i < 4; i++) {
        __half2 p = __floats2half2_rn(t[ri * 8 + 2 * i][c], t[ri * 8 + 2 * i + 1][c]);
        pk[i] = *(uint32_t*)&p;
    }
    size_t o = (size_t)(c0 + c) * R + r0 + ri * 8;
    *(uint4*)&P[o] = make_uint4(pk[0], pk[1], pk[2], pk[3]);
}

// ---------------- router ----------------
__global__ void k_router(const float* __restrict__ h, const float* __restrict__ rw) {
    int t = blockIdx.x;
    int lane = threadIdx.x & 31;
    int w = threadIdx.x >> 5;
    const float* hr = h + (size_t)t * Dn;
    float acc = 0.f;
    for (int d = lane; d < Dn; d += 32) acc += hr[d] * rw[d * En + w];
    #pragma unroll
    for (int o = 16; o; o >>= 1) acc += __shfl_xor_sync(0xFFFFFFFFu, acc, o);
    __shared__ float lg[En];
    if (lane == 0) lg[w] = acc;
    __syncthreads();
    if (threadIdx.x == 0) {
        float l[En];
        #pragma unroll
        for (int e = 0; e < En; e++) l[e] = lg[e];
        float m = l[0];
        #pragma unroll
        for (int e = 1; e < En; e++) m = fmaxf(m, l[e]);
        float p[En], s = 0.f;
        #pragma unroll
        for (int e = 0; e < En; e++) { p[e] = expf(l[e] - m); s += p[e]; }
        float inv = 1.0f / s;
        int i0 = 0;
        #pragma unroll
        for (int e = 1; e < En; e++) if (l[e] > l[i0]) i0 = e;
        int i1 = -1;
        #pragma unroll
        for (int e = 0; e < En; e++) {
            if (e == i0) continue;
            if (i1 < 0 || l[e] > l[i1]) i1 = e;
        }
        g_top2[2 * t] = i0;
        g_top2[2 * t + 1] = i1;
        g_topw[2 * t] = p[i0] * inv;
        g_topw[2 * t + 1] = p[i1] * inv;
        g_wkept[2 * t] = 0.f;
        g_wkept[2 * t + 1] = 0.f;
    }
}

// ---------------- capacity scan (smem-staged) ----------------
__global__ void k_scan() {
    __shared__ int s_top[Tn * 2];
    for (int i = threadIdx.x; i < Tn * 2; i += 256) s_top[i] = g_top2[i];
    __syncthreads();
    int lane = threadIdx.x & 31;
    int e = threadIdx.x >> 5;
    if (e >= En) return;
    int base = 0;
    for (int t0 = 0; t0 < Tn; t0 += 32) {
        int t = t0 + lane;
        int a = s_top[2 * t], b = s_top[2 * t + 1];
        int j = (a == e) ? 0 : ((b == e) ? 1 : -1);
        unsigned bal = __ballot_sync(0xFFFFFFFFu, j >= 0);
        int rank = base + __popc(bal & (0xFFFFFFFFu >> (31 - lane)));
        if (j >= 0 && rank <= CAPn) {
            int slot = rank - 1;
            g_elist[e * CAPn + slot] = t;
            float wv = g_topw[2 * t + j];
            g_ew[e * CAPn + slot] = wv;
            g_wkept[2 * t + j] = wv;
        }
        base += __popc(bal);
    }
    if (lane == 0) g_ecnt[e] = base < CAPn ? base : CAPn;
}

// ---------------- fused final rmsnorm -> fp16 (proj A operand) ----------------
__global__ void k_rms_fp16(const float* __restrict__ hin, const float* __restrict__ lnw,
                           __half* __restrict__ Ap) {
    int t = blockIdx.x;
    int lane = threadIdx.x & 31, wid = threadIdx.x >> 5;
    float4 v = ((const float4*)(hin + (size_t)t * Dn))[threadIdx.x];
    float s = v.x * v.x + v.y * v.y + v.z * v.z + v.w * v.w;
    #pragma unroll
    for (int o = 16; o; o >>= 1) s += __shfl_xor_sync(0xFFFFFFFFu, s, o);
    __shared__ float red[8];
    if (lane == 0) red[wid] = s;
    __syncthreads();
    float tot = 0.f;
    #pragma unroll
    for (int i = 0; i < 8; i++) tot += red[i];
    float sc = rsqrtf(tot * (1.0f / Dn) + 1e-6f);
    float4 w = ((const float4*)lnw)[threadIdx.x];
    __half2 a = __floats2half2_rn(v.x * sc * w.x, v.y * sc * w.y);
    __half2 b = __floats2half2_rn(v.z * sc * w.z, v.w * sc * w.w);
    ((uint2*)(Ap + (size_t)t * Dn))[threadIdx.x] = make_uint2(*(uint32_t*)&a, *(uint32_t*)&b);
}

// ================= HMMA tile framework =================
#define ROWB 80
#define ARRB (128 * ROWB)
#define STAGEB (4 * ARRB)
#define STAGE2B (2 * ARRB)

#define HMMA_PROLOG \
    extern __shared__ char smraw[]; \
    const uint32_t sbase = s2u(smraw); \
    const int tid = threadIdx.x; \
    const int lane = tid & 31; \
    const int wm = (tid >> 5) & 3; \
    const int wn = tid >> 7; \
    float acc[2][8][4]; \
    _Pragma("unroll") for (int i = 0; i < 2; i++) \
        _Pragma("unroll") for (int j = 0; j < 8; j++) \
            _Pragma("unroll") for (int q = 0; q < 4; q++) acc[i][j][q] = 0.f; \
    const int a_lr = lane & 15; \
    const int a_lc = ((lane >> 4) << 3); \
    const int b_nr = ((lane >> 4) << 3) + (lane & 7); \
    const int b_kc = (lane & 8);

#define HMMA_MAINLOOP(NCHKv) \
    load_stage(0, 0); \
    load_stage(1, 1); \
    for (int c = 0; c < (NCHKv); c++) { \
        const int st = c & 1; \
        if (c + 1 < (NCHKv)) asm volatile("cp.async.wait_group 1;" ::: "memory"); \
        else                 asm volatile("cp.async.wait_group 0;" ::: "memory"); \
        __syncthreads(); \
        const uint32_t sb = sbase + st * STAGEB; \
        _Pragma("unroll") \
        for (int k16 = 0; k16 < 32; k16 += 16) { \
            uint32_t ah[2][4], al[2][4]; \
            _Pragma("unroll") \
            for (int mi = 0; mi < 2; mi++) { \
                uint32_t aoff = (uint32_t)((wm * 32 + mi * 16 + a_lr) * ROWB + (k16 + a_lc) * 2); \
                ldsm4(ah[mi], sb + aoff); \
                ldsm4(al[mi], sb + ARRB + aoff); \
            } \
            _Pragma("unroll") \
            for (int ng = 0; ng < 4; ng++) { \
                uint32_t boff = (uint32_t)((wn * 64 + ng * 16 + b_nr) * ROWB + (k16 + b_kc) * 2); \
                uint32_t bh[4], bl[4]; \
                ldsm4(bh, sb + 2 * ARRB + boff); \
                ldsm4(bl, sb + 3 * ARRB + boff); \
                _Pragma("unroll") \
                for (int hv = 0; hv < 2; hv++) { \
                    const int nj = ng * 2 + hv; \
                    _Pragma("unroll") \
                    for (int mi = 0; mi < 2; mi++) { \
                        mma16816(acc[mi][nj], ah[mi], bh[2 * hv], bh[2 * hv + 1]); \
                        mma16816(acc[mi][nj], al[mi], bh[2 * hv], bh[2 * hv + 1]); \
                        mma16816(acc[mi][nj], ah[mi], bl[2 * hv], bl[2 * hv + 1]); \
                    } \
                } \
            } \
        } \
        __syncthreads(); \
        if (c + 2 < (NCHKv)) load_stage(c + 2, st); \
    }

#define HMMA16_MAINLOOP(NCHKv) \
    load_stage(0, 0); \
    load_stage(1, 1); \
    for (int c = 0; c < (NCHKv); c++) { \
        const int st = c & 1; \
        if (c + 1 < (NCHKv)) asm volatile("cp.async.wait_group 1;" ::: "memory"); \
        else                 asm volatile("cp.async.wait_group 0;" ::: "memory"); \
        __syncthreads(); \
        const uint32_t sb = sbase + st * STAGE2B; \
        _Pragma("unroll") \
        for (int k16 = 0; k16 < 32; k16 += 16) { \
            uint32_t af[2][4]; \
            _Pragma("unroll") \
            for (int mi = 0; mi < 2; mi++) { \
                uint32_t aoff = (uint32_t)((wm * 32 + mi * 16 + a_lr) * ROWB + (k16 + a_lc) * 2); \
                ldsm4(af[mi], sb + aoff); \
            } \
            _Pragma("unroll") \
            for (int ng = 0; ng < 4; ng++) { \
                uint32_t boff = (uint32_t)((wn * 64 + ng * 16 + b_nr) * ROWB + (k16 + b_kc) * 2); \
                uint32_t bf[4]; \
                ldsm4(bf, sb + ARRB + boff); \
                _Pragma("unroll") \
                for (int hv = 0; hv < 2; hv++) { \
                    const int nj = ng * 2 + hv; \
                    _Pragma("unroll") \
                    for (int mi = 0; mi < 2; mi++) \
                        mma16816h(acc[mi][nj], af[mi], bf[2 * hv], bf[2 * hv + 1]); \
                } \
            } \
        } \
        __syncthreads(); \
        if (c + 2 < (NCHKv)) load_stage(c + 2, st); \
    }

// ---------------- hop-1 GEMM1 (bf16 3-term) ----------------
__global__ __launch_bounds__(256, 2)
void k_gemm1_hmma(const __nv_bfloat16* __restrict__ Ah, const __nv_bfloat16* __restrict__ Al) {
    const int e = blockIdx.z;
    const int cnt = g_ecnt[e];
    const int m0 = blockIdx.y * 128;
    if (m0 >= cnt) return;
    HMMA_PROLOG
    const int n0 = blockIdx.x * 128;
    const __nv_bfloat16* Wh = g_w1h + (size_t)e * Fn * Dn;
    const __nv_bfloat16* Wl = g_w1l + (size_t)e * Fn * Dn;
    size_t gaA[2], gaB[2];
    uint32_t soff[2];
    #pragma unroll
    for (int hf = 0; hf < 2; hf++) {
        int id = tid + hf * 256;
        int row = id >> 2, seg = id & 3;
        int mrow = m0 + row;
        if (mrow >= cnt) mrow = cnt - 1;
        int tok = g_elist[e * CAPn + mrow];
        gaA[hf] = (size_t)tok * Dn + seg * 8;
        gaB[hf] = (size_t)(n0 + row) * Dn + seg * 8;
        soff[hf] = (uint32_t)(row * ROWB + seg * 16);
    }
    auto load_stage = [&](int c, int st) {
        const int kb = c * 32;
        const uint32_t sb = sbase + st * STAGEB;
        #pragma unroll
        for (int hf = 0; hf < 2; hf++) {
            cpa16(sb + soff[hf], Ah + gaA[hf] + kb);
            cpa16(sb + ARRB + soff[hf], Al + gaA[hf] + kb);
            cpa16(sb + 2 * ARRB + soff[hf], Wh + gaB[hf] + kb);
            cpa16(sb + 3 * ARRB + soff[hf], Wl + gaB[hf] + kb);
        }
        asm volatile("cp.async.commit_group;" ::: "memory");
    };
    HMMA_MAINLOOP(Dn / 32)
    __nv_bfloat16* Hh = g_hidh + (size_t)e * CAPn * Fn;
    __nv_bfloat16* Hl = g_hidl + (size_t)e * CAPn * Fn;
    const int g = lane >> 2, t2 = (lane & 3) << 1;
    #pragma unroll
    for (int mi = 0; mi < 2; mi++) {
        int r = wm * 32 + mi * 16 + g;
        #pragma unroll
        for (int nj = 0; nj < 8; nj++) {
            int col = n0 + wn * 64 + nj * 8 + t2;
            int s0 = m0 + r, s1 = m0 + r + 8;
            if (s0 < cnt) {
                float x0 = gelu_t(acc[mi][nj][0]), x1 = gelu_t(acc[mi][nj][1]);
                unsigned short h0, l0, h1, l1;
                bsplit(x0, h0, l0);
                bsplit(x1, h1, l1);
                *(uint32_t*)&Hh[(size_t)s0 * Fn + col] = (uint32_t)h0 | ((uint32_t)h1 << 16);
                *(uint32_t*)&Hl[(size_t)s0 * Fn + col] = (uint32_t)l0 | ((uint32_t)l1 << 16);
            }
            if (s1 < cnt) {
                float x2 = gelu_t(acc[mi][nj][2]), x3 = gelu_t(acc[mi][nj][3]);
                unsigned short h2, l2, h3, l3;
                bsplit(x2, h2, l2);
                bsplit(x3, h3, l3);
                *(uint32_t*)&Hh[(size_t)s1 * Fn + col] = (uint32_t)h2 | ((uint32_t)h3 << 16);
                *(uint32_t*)&Hl[(size_t)s1 * Fn + col] = (uint32_t)l2 | ((uint32_t)l3 << 16);
            }
        }
    }
}

// ---------------- hop-1 GEMM2 (bf16 3-term): scatter ----------------
__global__ __launch_bounds__(256, 2)
void k_gemm2_hmma(float* __restrict__ hout) {
    const int e = blockIdx.z;
    const int cnt = g_ecnt[e];
    const int m0 = blockIdx.y * 128;
    if (m0 >= cnt) return;
    HMMA_PROLOG
    const int n0 = blockIdx.x * 128;
    const __nv_bfloat16* Ahp = g_hidh + (size_t)e * CAPn * Fn;
    const __nv_bfloat16* Alp = g_hidl + (size_t)e * CAPn * Fn;
    const __nv_bfloat16* Wh = g_w2h + (size_t)e * Dn * Fn;
    const __nv_bfloat16* Wl = g_w2l + (size_t)e * Dn * Fn;
    size_t gaA[2], gaB[2];
    uint32_t soff[2];
    #pragma unroll
    for (int hf = 0; hf < 2; hf++) {
        int id = tid + hf * 256;
        int row = id >> 2, seg = id & 3;
        gaA[hf] = (size_t)(m0 + row) * Fn + seg * 8;
        gaB[hf] = (size_t)(n0 + row) * Fn + seg * 8;
        soff[hf] = (uint32_t)(row * ROWB + seg * 16);
    }
    auto load_stage = [&](int c, int st) {
        const int kb = c * 32;
        const uint32_t sb = sbase + st * STAGEB;
        #pragma unroll
        for (int hf = 0; hf < 2; hf++) {
            cpa16(sb + soff[hf], Ahp + gaA[hf] + kb);
            cpa16(sb + ARRB + soff[hf], Alp + gaA[hf] + kb);
            cpa16(sb + 2 * ARRB + soff[hf], Wh + gaB[hf] + kb);
            cpa16(sb + 3 * ARRB + soff[hf], Wl + gaB[hf] + kb);
        }
        asm volatile("cp.async.commit_group;" ::: "memory");
    };
    HMMA_MAINLOOP(Fn / 32)
    const int g = lane >> 2, t2 = (lane & 3) << 1;
    #pragma unroll
    for (int mi = 0; mi < 2; mi++) {
        int r = wm * 32 + mi * 16 + g;
        int s0 = m0 + r, s1 = m0 + r + 8;
        int tok0 = 0, tok1 = 0;
        float w0 = 0.f, w1v = 0.f;
        if (s0 < cnt) { tok0 = g_elist[e * CAPn + s0]; w0 = g_ew[e * CAPn + s0]; }
        if (s1 < cnt) { tok1 = g_elist[e * CAPn + s1]; w1v = g_ew[e * CAPn + s1]; }
        #pragma unroll
        for (int nj = 0; nj < 8; nj++) {
            int col = n0 + wn * 64 + nj * 8 + t2;
            if (s0 < cnt) {
                atomicAdd(&hout[(size_t)tok0 * Dn + col], w0 * acc[mi][nj][0]);
                atomicAdd(&hout[(size_t)tok0 * Dn + col + 1], w0 * acc[mi][nj][1]);
            }
            if (s1 < cnt) {
                atomicAdd(&hout[(size_t)tok1 * Dn + col], w1v * acc[mi][nj][2]);
                atomicAdd(&hout[(size_t)tok1 * Dn + col + 1], w1v * acc[mi][nj][3]);
            }
        }
    }
}

// ---------------- hop-2 GEMM1 (fp16 single) ----------------
__global__ __launch_bounds__(256, 2)
void k_gemm1_fp16(const __half* __restrict__ Ap) {
    const int e = blockIdx.z;
    const int cnt = g_ecnt[e];
    const int m0 = blockIdx.y * 128;
    if (m0 >= cnt) return;
    HMMA_PROLOG
    const int n0 = blockIdx.x * 128;
    const __half* Wp = g_w1p + (size_t)e * Fn * Dn;
    size_t gaA[2], gaB[2];
    uint32_t soff[2];
    #pragma unroll
    for (int hf = 0; hf < 2; hf++) {
        int id = tid + hf * 256;
        int row = id >> 2, seg = id & 3;
        int mrow = m0 + row;
        if (mrow >= cnt) mrow = cnt - 1;
        int tok = g_elist[e * CAPn + mrow];
        gaA[hf] = (size_t)tok * Dn + seg * 8;
        gaB[hf] = (size_t)(n0 + row) * Dn + seg * 8;
        soff[hf] = (uint32_t)(row * ROWB + seg * 16);
    }
    auto load_stage = [&](int c, int st) {
        const int kb = c * 32;
        const uint32_t sb = sbase + st * STAGE2B;
        #pragma unroll
        for (int hf = 0; hf < 2; hf++) {
            cpa16(sb + soff[hf], Ap + gaA[hf] + kb);
            cpa16(sb + ARRB + soff[hf], Wp + gaB[hf] + kb);
        }
        asm volatile("cp.async.commit_group;" ::: "memory");
    };
    HMMA16_MAINLOOP(Dn / 32)
    __half* Hp = g_hidp + (size_t)e * CAPn * Fn;
    const int g = lane >> 2, t2 = (lane & 3) << 1;
    #pragma unroll
    for (int mi = 0; mi < 2; mi++) {
        int r = wm * 32 + mi * 16 + g;
        #pragma unroll
        for (int nj = 0; nj < 8; nj++) {
            int col = n0 + wn * 64 + nj * 8 + t2;
            int s0 = m0 + r, s1 = m0 + r + 8;
            if (s0 < cnt) {
                __half2 p = __floats2half2_rn(gelu_t(acc[mi][nj][0]), gelu_t(acc[mi][nj][1]));
                *(uint32_t*)&Hp[(size_t)s0 * Fn + col] = *(uint32_t*)&p;
            }
            if (s1 < cnt) {
                __half2 p = __floats2half2_rn(gelu_t(acc[mi][nj][2]), gelu_t(acc[mi][nj][3]));
                *(uint32_t*)&Hp[(size_t)s1 * Fn + col] = *(uint32_t*)&p;
            }
        }
    }
}

// ---------------- hop-2 GEMM2 (fp16 single): scatter ----------------
__global__ __launch_bounds__(256, 2)
void k_gemm2_fp16(float* __restrict__ hout) {
    const int e = blockIdx.z;
    const int cnt = g_ecnt[e];
    const int m0 = blockIdx.y * 128;
    if (m0 >= cnt) return;
    HMMA_PROLOG
    const int n0 = blockIdx.x * 128;
    const __half* Apx = g_hidp + (size_t)e * CAPn * Fn;
    const __half* Wp = g_w2p + (size_t)e * Dn * Fn;
    size_t gaA[2], gaB[2];
    uint32_t soff[2];
    #pragma unroll
    for (int hf = 0; hf < 2; hf++) {
        int id = tid + hf * 256;
        int row = id >> 2, seg = id & 3;
        gaA[hf] = (size_t)(m0 + row) * Fn + seg * 8;
        gaB[hf] = (size_t)(n0 + row) * Fn + seg * 8;
        soff[hf] = (uint32_t)(row * ROWB + seg * 16);
    }
    auto load_stage = [&](int c, int st) {
        const int kb = c * 32;
        const uint32_t sb = sbase + st * STAGE2B;
        #pragma unroll
        for (int hf = 0; hf < 2; hf++) {
            cpa16(sb + soff[hf], Apx + gaA[hf] + kb);
            cpa16(sb + ARRB + soff[hf], Wp + gaB[hf] + kb);
        }
        asm volatile("cp.async.commit_group;" ::: "memory");
    };
    HMMA16_MAINLOOP(Fn / 32)
    const int g = lane >> 2, t2 = (lane & 3) << 1;
    #pragma unroll
    for (int mi = 0; mi < 2; mi++) {
        int r = wm * 32 + mi * 16 + g;
        int s0 = m0 + r, s1 = m0 + r + 8;
        int tok0 = 0, tok1 = 0;
        float w0 = 0.f, w1v = 0.f;
        if (s0 < cnt) { tok0 = g_elist[e * CAPn + s0]; w0 = g_ew[e * CAPn + s0]; }
        if (s1 < cnt) { tok1 = g_elist[e * CAPn + s1]; w1v = g_ew[e * CAPn + s1]; }
        #pragma unroll
        for (int nj = 0; nj < 8; nj++) {
            int col = n0 + wn * 64 + nj * 8 + t2;
            if (s0 < cnt) {
                atomicAdd(&hout[(size_t)tok0 * Dn + col], w0 * acc[mi][nj][0]);
                atomicAdd(&hout[(size_t)tok0 * Dn + col + 1], w0 * acc[mi][nj][1]);
            }
            if (s1 < cnt) {
                atomicAdd(&hout[(size_t)tok1 * Dn + col], w1v * acc[mi][nj][2]);
                atomicAdd(&hout[(size_t)tok1 * Dn + col + 1], w1v * acc[mi][nj][3]);
            }
        }
    }
}

// ---------------- tied projection (fp16 single): C = Ap . Bp^T ----------------
__global__ __launch_bounds__(256, 2)
void k_proj_fp16(const __half* __restrict__ Ap, const __half* __restrict__ Bp,
                 float* __restrict__ C) {
    HMMA_PROLOG
    const int m0 = blockIdx.x * 128;
    const int n0 = blockIdx.y * 128;
    size_t gaA[2], gaB[2];
    uint32_t soff[2];
    #pragma unroll
    for (int hf = 0; hf < 2; hf++) {
        int id = tid + hf * 256;
        int row = id >> 2, seg = id & 3;
        gaA[hf] = (size_t)(m0 + row) * Dn + seg * 8;
        gaB[hf] = (size_t)(n0 + row) * Dn + seg * 8;
        soff[hf] = (uint32_t)(row * ROWB + seg * 16);
    }
    auto load_stage = [&](int c, int st) {
        const int kb = c * 32;
        const uint32_t sb = sbase + st * STAGE2B;
        #pragma unroll
        for (int hf = 0; hf < 2; hf++) {
            cpa16(sb + soff[hf], Ap + gaA[hf] + kb);
            cpa16(sb + ARRB + soff[hf], Bp + gaB[hf] + kb);
        }
        asm volatile("cp.async.commit_group;" ::: "memory");
    };
    HMMA16_MAINLOOP(Dn / 32)
    const int g = lane >> 2, t2 = (lane & 3) << 1;
    #pragma unroll
    for (int mi = 0; mi < 2; mi++) {
        #pragma unroll
        for (int nj = 0; nj < 8; nj++) {
            int r = m0 + wm * 32 + mi * 16 + g;
            int col = n0 + wn * 64 + nj * 8 + t2;
            *(float2*)&C[(size_t)r * Vn + col] = make_float2(acc[mi][nj][0], acc[mi][nj][1]);
            *(float2*)&C[(size_t)(r + 8) * Vn + col] = make_float2(acc[mi][nj][2], acc[mi][nj][3]);
        }
    }
}

// ---------------- launch ----------------
extern "C" void kernel_launch(void* const* d_in, const int* in_sizes, int n_in,
                              void* d_out, int out_size) {
    (void)in_sizes; (void)n_in; (void)out_size;
    const int*   ids    = (const int*)d_in[0];
    const float* embed  = (const float*)d_in[1];
    const float* router = (const float*)d_in[2];
    const float* w1     = (const float*)d_in[3];
    const float* w2     = (const float*)d_in[4];
    const float* lnw    = (const float*)d_in[5];
    float* out = (float*)d_out;

    float *hA, *hB;
    __half *pBp, *pAp, *pw1p, *pw2p;
    __nv_bfloat16 *pAh, *pAl, *pw1h, *pw1l, *pw2h, *pw2l;
    cudaGetSymbolAddress((void**)&hA, g_hA);
    cudaGetSymbolAddress((void**)&hB, g_hB);
    cudaGetSymbolAddress((void**)&pBp, g_Bp);
    cudaGetSymbolAddress((void**)&pAh, g_Ah);
    cudaGetSymbolAddress((void**)&pAl, g_Al);
    cudaGetSymbolAddress((void**)&pAp, g_Ap);
    cudaGetSymbolAddress((void**)&pw1h, g_w1h);
    cudaGetSymbolAddress((void**)&pw1l, g_w1l);
    cudaGetSymbolAddress((void**)&pw1p, g_w1p);
    cudaGetSymbolAddress((void**)&pw2h, g_w2h);
    cudaGetSymbolAddress((void**)&pw2l, g_w2l);
    cudaGetSymbolAddress((void**)&pw2p, g_w2p);

    static cudaStream_t s2 = nullptr;
    static cudaEvent_t evFork, evW1b, evW2b, evW1p, evW2p, evBp;
    if (!s2) {
        cudaStreamCreateWithFlags(&s2, cudaStreamNonBlocking);
        cudaEventCreateWithFlags(&evFork, cudaEventDisableTiming);
        cudaEventCreateWithFlags(&evW1b, cudaEventDisableTiming);
        cudaEventCreateWithFlags(&evW2b, cudaEventDisableTiming);
        cudaEventCreateWithFlags(&evW1p, cudaEventDisableTiming);
        cudaEventCreateWithFlags(&evW2p, cudaEventDisableTiming);
        cudaEventCreateWithFlags(&evBp, cudaEventDisableTiming);
        cudaFuncSetAttribute(k_gemm1_hmma, cudaFuncAttributeMaxDynamicSharedMemorySize, 2 * STAGEB);
        cudaFuncSetAttribute(k_gemm2_hmma, cudaFuncAttributeMaxDynamicSharedMemorySize, 2 * STAGEB);
        cudaFuncSetAttribute(k_gemm1_fp16, cudaFuncAttributeMaxDynamicSharedMemorySize, 2 * STAGE2B);
        cudaFuncSetAttribute(k_gemm2_fp16, cudaFuncAttributeMaxDynamicSharedMemorySize, 2 * STAGE2B);
        cudaFuncSetAttribute(k_proj_fp16, cudaFuncAttributeMaxDynamicSharedMemorySize, 2 * STAGE2B);
    }

    // ---- fork: weight prep on side stream (memory-bound; overlaps tensor work) ----
    cudaEventRecord(evFork, 0);
    cudaStreamWaitEvent(s2, evFork, 0);
    k_tsplit_bf<<<dim3(Fn / 32, Dn / 64, En), 256, 0, s2>>>(w1, pw1h, pw1l, Dn, Fn);
    cudaEventRecord(evW1b, s2);
    k_tsplit_bf<<<dim3(Dn / 32, Fn / 64, En), 256, 0, s2>>>(w2, pw2h, pw2l, Fn, Dn);
    cudaEventRecord(evW2b, s2);
    k_tsplit_fp<<<dim3(Fn / 32, Dn / 64, En), 256, 0, s2>>>(w1, pw1p, Dn, Fn);
    cudaEventRecord(evW1p, s2);
    k_tsplit_fp<<<dim3(Dn / 32, Fn / 64, En), 256, 0, s2>>>(w2, pw2p, Fn, Dn);
    cudaEventRecord(evW2p, s2);
    k_cvt16<<<(Vn * Dn / 4 + 255) / 256, 256, 0, s2>>>(embed, pBp, Vn * Dn / 4);
    cudaEventRecord(evBp, s2);

    // ---- main chain ----
    k_embed<<<(Tn * Dn / 4) / 256, 256>>>(ids, embed);

    float* hin = hA;
    float* hout = hB;
    for (int hop = 0; hop < 2; hop++) {
        k_router<<<Tn, 256>>>(hin, router + (size_t)hop * Dn * En);
        k_scan<<<1, 256>>>();
        k_prep_h<<<Tn, 256>>>(hin, hout, pAh, pAl, pAp, hop);
        if (hop == 0) {
            cudaStreamWaitEvent(0, evW1b, 0);
            k_gemm1_hmma<<<dim3(Fn / 128, (CAPn + 127) / 128, En), 256, 2 * STAGEB>>>(pAh, pAl);
            cudaStreamWaitEvent(0, evW2b, 0);
            k_gemm2_hmma<<<dim3(Dn / 128, (CAPn + 127) / 128, En), 256, 2 * STAGEB>>>(hout);
        } else {
            cudaStreamWaitEvent(0, evW1p, 0);
            k_gemm1_fp16<<<dim3(Fn / 128, (CAPn + 127) / 128, En), 256, 2 * STAGE2B>>>(pAp);
            cudaStreamWaitEvent(0, evW2p, 0);
            k_gemm2_fp16<<<dim3(Dn / 128, (CAPn + 127) / 128, En), 256, 2 * STAGE2B>>>(hout);
        }
        float* tmp = hin; hin = hout; hout = tmp;
    }
    k_rms_fp16<<<Tn, 256>>>(hin, lnw, pAp);

    cudaStreamWaitEvent(0, evBp, 0);
    k_proj_fp16<<<dim3(Tn / 128, Vn / 128), 256, 2 * STAGE2B>>>(pAp, pBp, out);
}